// round 13
// baseline (speedup 1.0000x reference)
#include <cuda_runtime.h>
#include <math.h>

// ---------------------------------------------------------------------------
// InteractionPredictor: e3nn-style equivariant GNN, fully fused fp32.
// R12: k_msg/k_lig use 128 edges / 256 threads, 4 edge-slots/lane, and each
// of the 8 warps covers its k=8 rows in TWO passes of KC=4 (h[4][4] only
// -> fold fits the 128-reg cap; weight-LDG per edge stays halved vs R9).
// Reductions (4-feature non-atomic slices + tree-add) run once per pass;
// g_msgs / g_lig accumulate across passes via atomicAdd. k_rec as in R9.
// ---------------------------------------------------------------------------

#define TBE    256         /* threads per edge block      */
#define EPB    128         /* edges per block (msg/lig)   */
#define EPR    128         /* edges per block (rec)       */
#define KCP    4           /* k-rows per warp per pass    */
#define NPASS  2           /* passes (8 warps*4*2 = 64 k) */
#define KC     8           /* k-chunk per warp (k_rec)    */
#define NW     8           /* warps per block             */
#define NF     40
#define NMAX   16384
#define EIMAX  65536

__device__ float g_node[NMAX * NF];
__device__ float g_msgs[NMAX * NF];
__device__ float g_lig [EIMAX * NF];

#define C24    0.20412414523193154f   /* sqrt(1/24)  */
#define C24S3  0.35355339059327373f   /* sqrt(1/8)   */
#define INVS3  0.57735026918962576f   /* 1/sqrt(3)   */
#define PWREC  0.05590169943749474f   /* 1/sqrt(320) */
#define DEMBC  8.4335731f             /* 1.14136*e^2 */
#define INV32  0.17677669529663687f   /* 1/sqrt(32)  */

__device__ __forceinline__ float siluN(float x) {
    return x * (1.0f / (1.0f + __expf(-x))) * 1.6789717f;
}

// ---------------------------------------------------------------------------
// node embedding; also zeroes the message accumulator for step 0
// ---------------------------------------------------------------------------
__global__ void k_embed(const float* __restrict__ x, int N, int A,
                        const float* __restrict__ W0, const float* __restrict__ W1) {
    int n = blockIdx.x * blockDim.x + threadIdx.x;
    if (n >= N) return;
    float inv = rsqrtf((float)A);
    float a[16];
#pragma unroll
    for (int b = 0; b < 16; b++) a[b] = (b < A) ? x[n * A + b] : 0.0f;
    float h[64];
#pragma unroll 4
    for (int k = 0; k < 64; k++) {
        float s = 0.0f;
#pragma unroll
        for (int b = 0; b < 16; b++)
            if (b < A) s += a[b] * W0[b * 64 + k];
        h[k] = siluN(s * inv) * 0.125f;
    }
    float* nr = g_node + n * NF;
#pragma unroll
    for (int w = 0; w < 16; w++) {
        float s = 0.0f;
#pragma unroll 8
        for (int k = 0; k < 64; k++) s += h[k] * W1[k * 16 + w];
        nr[w] = s;
    }
#pragma unroll
    for (int t = 0; t < 24; t++) nr[16 + t] = 0.0f;
    float* mr = g_msgs + n * NF;
#pragma unroll
    for (int t = 0; t < NF; t++) mr[t] = 0.0f;
}

// ---------------------------------------------------------------------------
// node update; re-zeroes this node's message row after consuming it
// ---------------------------------------------------------------------------
__global__ void k_update(int N, const float* __restrict__ imp, float degf,
                         const float* __restrict__ W0, const float* __restrict__ W1,
                         float gmul) {
    int n = blockIdx.x * blockDim.x + threadIdx.x;
    if (n >= N) return;
    float scale = imp[0] * rsqrtf(degf);
    float* nr = g_node + n * NF;
    float* mr = g_msgs + n * NF;
    float a[32];
#pragma unroll
    for (int t = 0; t < 16; t++) a[t] = mr[t] * scale;
#pragma unroll
    for (int t = 0; t < 16; t++) a[16 + t] = nr[t];
    float ge[24];
#pragma unroll
    for (int t = 0; t < 24; t++) ge[t] = (mr[16 + t] * scale + nr[16 + t]) * gmul;
#pragma unroll
    for (int t = 0; t < NF; t++) mr[t] = 0.0f;
    float h[64];
#pragma unroll 2
    for (int k = 0; k < 64; k++) {
        float s = 0.0f;
#pragma unroll
        for (int b = 0; b < 32; b++) s += a[b] * W0[b * 64 + k];
        h[k] = siluN(s * INV32) * 0.125f;
    }
    float sc[16];
#pragma unroll
    for (int w = 0; w < 16; w++) {
        float s = 0.0f;
#pragma unroll 8
        for (int k = 0; k < 64; k++) s += h[k] * W1[k * 16 + w];
        sc[w] = s;
    }
#pragma unroll
    for (int w = 0; w < 16; w++) nr[w] = sc[w];
#pragma unroll
    for (int t = 0; t < 24; t++) nr[16 + t] = ge[t];
}

// ---------------------------------------------------------------------------
__device__ __forceinline__ void demb_compute(float d, float* a) {
    float tt = d * 4.2f;
#pragma unroll
    for (int i = 0; i < 20; i++) {
        float diff = tt - (float)(i + 1);
        float p = diff + 1.0f, q = 1.0f - diff;
        float s1 = (p > 0.0f) ? __expf(-1.0f / p) : 0.0f;
        float s2 = (q > 0.0f) ? __expf(-1.0f / q) : 0.0f;
        a[i] = DEMBC * s1 * s2;
    }
}

// ---------------------------------------------------------------------------
// Scalar fold, one column-half (8 of 16 outputs), 4 slots, KCP=4 k-rows.
// ---------------------------------------------------------------------------
__device__ __forceinline__ void fold_scalar_half4(
    const float h[4][KCP], int lane, int half,
    const float* __restrict__ shN, const float* __restrict__ shR,
    const float* __restrict__ W1k, float os[4][8])
{
#pragma unroll
    for (int s = 0; s < 4; s++)
#pragma unroll
        for (int t = 0; t < 8; t++) os[s][t] = 0.0f;

    // Block A: cols u*16 + half*8, u<16 ; cf = C24 * xs_u
#pragma unroll 1
    for (int u = 0; u < 16; u++) {
        float cf[4];
#pragma unroll
        for (int s = 0; s < 4; s++) cf[s] = C24 * shN[u * EPB + lane + s * 32];
#pragma unroll
        for (int j = 0; j < KCP; j++) {
            float p[4];
#pragma unroll
            for (int s = 0; s < 4; s++) p[s] = cf[s] * h[s][j];
            const float4* bp = reinterpret_cast<const float4*>(W1k + j * 576 + u * 16 + half * 8);
            float4 q0 = __ldg(bp), q1 = __ldg(bp + 1);
#pragma unroll
            for (int s = 0; s < 4; s++) {
                os[s][0] += p[s] * q0.x; os[s][1] += p[s] * q0.y;
                os[s][2] += p[s] * q0.z; os[s][3] += p[s] * q0.w;
                os[s][4] += p[s] * q1.x; os[s][5] += p[s] * q1.y;
                os[s][6] += p[s] * q1.z; os[s][7] += p[s] * q1.w;
            }
        }
    }

    // Block B: cols 256 + u*16 + half*8, u<8 ; cf = C24 * (xv_u . r)
#pragma unroll 1
    for (int u = 0; u < 8; u++) {
        float cf[4];
#pragma unroll
        for (int s = 0; s < 4; s++) {
            int idx = lane + s * 32;
            cf[s] = C24 * (shN[(16 + u * 3) * EPB + idx] * shR[idx] +
                           shN[(17 + u * 3) * EPB + idx] * shR[EPB + idx] +
                           shN[(18 + u * 3) * EPB + idx] * shR[2 * EPB + idx]);
        }
#pragma unroll
        for (int j = 0; j < KCP; j++) {
            float p[4];
#pragma unroll
            for (int s = 0; s < 4; s++) p[s] = cf[s] * h[s][j];
            const float4* bp = reinterpret_cast<const float4*>(W1k + j * 576 + 256 + u * 16 + half * 8);
            float4 q0 = __ldg(bp), q1 = __ldg(bp + 1);
#pragma unroll
            for (int s = 0; s < 4; s++) {
                os[s][0] += p[s] * q0.x; os[s][1] += p[s] * q0.y;
                os[s][2] += p[s] * q0.z; os[s][3] += p[s] * q0.w;
                os[s][4] += p[s] * q1.x; os[s][5] += p[s] * q1.y;
                os[s][6] += p[s] * q1.z; os[s][7] += p[s] * q1.w;
            }
        }
    }
}

// ---------------------------------------------------------------------------
// Vector fold, one half (t 0..3 or 4..7 -> 12 features), 4 slots, KCP=4.
// Block C r-factored (cpre expanded by r at end), block D direct.
// ---------------------------------------------------------------------------
__device__ __forceinline__ void fold_vector_half4(
    const float h[4][KCP], int lane, int half,
    const float* __restrict__ shN, const float* __restrict__ shR,
    const float* __restrict__ W1k, float ov[4][12])
{
    // --- Block C (factored) ---
    float cpre[4][4];
#pragma unroll
    for (int s = 0; s < 4; s++)
#pragma unroll
        for (int t = 0; t < 4; t++) cpre[s][t] = 0.0f;

#pragma unroll 1
    for (int u = 0; u < 16; u++) {
        float cf[4];
#pragma unroll
        for (int s = 0; s < 4; s++) cf[s] = C24S3 * shN[u * EPB + lane + s * 32];
#pragma unroll
        for (int j = 0; j < KCP; j++) {
            float p[4];
#pragma unroll
            for (int s = 0; s < 4; s++) p[s] = cf[s] * h[s][j];
            float4 q = __ldg(reinterpret_cast<const float4*>(W1k + j * 576 + 384 + u * 8 + half * 4));
#pragma unroll
            for (int s = 0; s < 4; s++) {
                cpre[s][0] += p[s] * q.x; cpre[s][1] += p[s] * q.y;
                cpre[s][2] += p[s] * q.z; cpre[s][3] += p[s] * q.w;
            }
        }
    }

    // expand by r
#pragma unroll
    for (int s = 0; s < 4; s++) {
        int idx = lane + s * 32;
        float r0 = shR[idx], r1 = shR[EPB + idx], r2 = shR[2 * EPB + idx];
#pragma unroll
        for (int t = 0; t < 4; t++) {
            ov[s][t * 3 + 0] = cpre[s][t] * r0;
            ov[s][t * 3 + 1] = cpre[s][t] * r1;
            ov[s][t * 3 + 2] = cpre[s][t] * r2;
        }
    }

    // --- Block D ---
#pragma unroll 1
    for (int u = 0; u < 8; u++) {
        float c0[4], c1[4], c2[4];
#pragma unroll
        for (int s = 0; s < 4; s++) {
            int idx = lane + s * 32;
            c0[s] = C24 * shN[(16 + u * 3) * EPB + idx];
            c1[s] = C24 * shN[(17 + u * 3) * EPB + idx];
            c2[s] = C24 * shN[(18 + u * 3) * EPB + idx];
        }
#pragma unroll
        for (int j = 0; j < KCP; j++) {
            float4 q = __ldg(reinterpret_cast<const float4*>(W1k + j * 576 + 512 + u * 8 + half * 4));
            float qa[4] = {q.x, q.y, q.z, q.w};
#pragma unroll
            for (int t = 0; t < 4; t++) {
#pragma unroll
                for (int s = 0; s < 4; s++) {
                    float tv = h[s][j] * qa[t];
                    ov[s][t * 3 + 0] += c0[s] * tv;
                    ov[s][t * 3 + 1] += c1[s] * tv;
                    ov[s][t * 3 + 2] += c2[s] * tv;
                }
            }
        }
    }
}

// ---------------------------------------------------------------------------
// message kernel: 128 edges / 256 threads, 8 warps, 4 slots/lane, 2 k-passes
// ---------------------------------------------------------------------------
__global__ void __launch_bounds__(TBE, 2) k_msg(
    const float* __restrict__ pos,
    const int* __restrict__ srcI, const int* __restrict__ dstI,
    const float* __restrict__ eattr, int E, int B,
    const float* __restrict__ W0, const float* __restrict__ W1)
{
    __shared__ float shN[NF * EPB];          // 20 KB
    __shared__ float shS[NW * 4 * EPB];      // 16 KB
    __shared__ float shR[3 * EPB];           // 1.5 KB
    __shared__ int   shSi[EPB];
    __shared__ int   shDi[EPB];

    int tid  = threadIdx.x;
    int lane = tid & 31;
    int warp = tid >> 5;
    int e0 = blockIdx.x * EPB;

    if (tid < EPB) {
        int e = min(e0 + tid, E - 1);
        int si = srcI[e], di = dstI[e];
        shSi[tid] = si; shDi[tid] = di;
        float vx = pos[di * 3 + 0] - pos[si * 3 + 0];
        float vy = pos[di * 3 + 1] - pos[si * 3 + 1];
        float vz = pos[di * 3 + 2] - pos[si * 3 + 2];
        float rn = rsqrtf(vx * vx + vy * vy + vz * vz);
        shR[tid]           = vx * rn;
        shR[EPB + tid]     = vy * rn;
        shR[2 * EPB + tid] = vz * rn;
    }
    __syncthreads();

    for (int i = tid; i < NF * EPB; i += TBE) {
        int e = i & (EPB - 1), f = i >> 7;
        shN[f * EPB + e] = g_node[shSi[e] * NF + f];
    }
    __syncthreads();

#pragma unroll 1
    for (int pass = 0; pass < NPASS; pass++) {
        int kb = warp * KCP + pass * 32;
        const float* W1k = W1 + kb * 576;

        // this warp's KCP rows of h for this pass (4 edge-slots)
        float h[4][KCP];
        {
            float inv = rsqrtf((float)B);
#pragma unroll
            for (int s = 0; s < 4; s++) {
                int e = min(e0 + lane + s * 32, E - 1);
                float aa[8];
#pragma unroll
                for (int b = 0; b < 8; b++) aa[b] = (b < B) ? eattr[e * B + b] : 0.0f;
#pragma unroll
                for (int j = 0; j < KCP; j++) {
                    float sm = 0.0f;
#pragma unroll
                    for (int b = 0; b < 8; b++)
                        if (b < B) sm += aa[b] * W0[b * 64 + kb + j];
                    h[s][j] = siluN(sm * inv) * 0.125f;
                }
            }
        }

        // ---- scalar halves; dump each os[4][8] in 2 chunks of 4 features ----
#pragma unroll 1
        for (int half = 0; half < 2; half++) {
            float os[4][8];
            fold_scalar_half4(h, lane, half, shN, shR, W1k, os);
#pragma unroll 1
            for (int c = 0; c < 2; c++) {
                __syncthreads();
#pragma unroll
                for (int f = 0; f < 4; f++)
#pragma unroll
                    for (int s = 0; s < 4; s++)
                        shS[warp * 4 * EPB + f * EPB + lane + s * 32] = os[s][c * 4 + f];
                __syncthreads();
                for (int i = tid; i < 4 * EPB; i += TBE) {
                    float sm = 0.0f;
#pragma unroll
                    for (int w = 0; w < NW; w++) sm += shS[w * 4 * EPB + i];
                    int e = i & (EPB - 1), f = i >> 7;
                    if (e0 + e < E)
                        atomicAdd(&g_msgs[shDi[e] * NF + half * 8 + c * 4 + f], sm);
                }
            }
        }

        // ---- vector halves; dump each ov[4][12] in 3 chunks of 4 features ----
#pragma unroll 1
        for (int half = 0; half < 2; half++) {
            float ov[4][12];
            fold_vector_half4(h, lane, half, shN, shR, W1k, ov);
#pragma unroll 1
            for (int c = 0; c < 3; c++) {
                __syncthreads();
#pragma unroll
                for (int f = 0; f < 4; f++)
#pragma unroll
                    for (int s = 0; s < 4; s++)
                        shS[warp * 4 * EPB + f * EPB + lane + s * 32] = ov[s][c * 4 + f];
                __syncthreads();
                for (int i = tid; i < 4 * EPB; i += TBE) {
                    float sm = 0.0f;
#pragma unroll
                    for (int w = 0; w < NW; w++) sm += shS[w * 4 * EPB + i];
                    int e = i & (EPB - 1), f = i >> 7;
                    if (e0 + e < E)
                        atomicAdd(&g_msgs[shDi[e] * NF + 16 + half * 12 + c * 4 + f], sm);
                }
            }
        }
    }
}

// ---------------------------------------------------------------------------
// ligand embedding: same structure; g_lig rows zeroed then accumulated via
// atomics across the 2 passes. Also zeroes d_out rows for k_rec.
// ---------------------------------------------------------------------------
__global__ void __launch_bounds__(TBE, 2) k_lig(
    const float* __restrict__ pos,
    const int* __restrict__ recI, const int* __restrict__ ligI, int EI,
    const float* __restrict__ W0, const float* __restrict__ W1,
    float* __restrict__ out)
{
    __shared__ float shN[NF * EPB];
    __shared__ float shS[NW * 4 * EPB];
    __shared__ float shR[3 * EPB];
    __shared__ float shD[EPB];
    __shared__ int   shLi[EPB];

    int tid  = threadIdx.x;
    int lane = tid & 31;
    int warp = tid >> 5;
    int e0 = blockIdx.x * EPB;

    // zero own output rows (d_out for k_rec) and own g_lig rows
    for (int i = tid; i < 8 * EPB; i += TBE) {
        int e = i >> 3;
        if (e0 + e < EI) out[(e0 + e) * 8 + (i & 7)] = 0.0f;
    }
    for (int i = tid; i < NF * EPB; i += TBE) {
        int e = i >> 5;           // i / 32? careful: use div by NF instead
        // (use straightforward indexing below)
        ;
    }
    for (int i = tid; i < NF * EPB; i += TBE) {
        int e = i / NF, f = i - e * NF;
        if (e0 + e < EI) g_lig[(e0 + e) * NF + f] = 0.0f;
    }

    if (tid < EPB) {
        int e = min(e0 + tid, EI - 1);
        int ri = recI[e], li = ligI[e];
        shLi[tid] = li;
        float vx = pos[li * 3 + 0] - pos[ri * 3 + 0];
        float vy = pos[li * 3 + 1] - pos[ri * 3 + 1];
        float vz = pos[li * 3 + 2] - pos[ri * 3 + 2];
        float d2 = vx * vx + vy * vy + vz * vz;
        float invd = rsqrtf(d2);
        shR[tid]           = vx * invd;
        shR[EPB + tid]     = vy * invd;
        shR[2 * EPB + tid] = vz * invd;
        shD[tid]           = d2 * invd;
    }
    __syncthreads();

    for (int i = tid; i < NF * EPB; i += TBE) {
        int e = i & (EPB - 1), f = i >> 7;
        shN[f * EPB + e] = g_node[shLi[e] * NF + f];
    }
    __syncthreads();

#pragma unroll 1
    for (int pass = 0; pass < NPASS; pass++) {
        int kb = warp * KCP + pass * 32;
        const float* W1k = W1 + kb * 576;

        float h[4][KCP];
#pragma unroll 1
        for (int s = 0; s < 4; s++) {
            float aa[20];
            demb_compute(shD[lane + s * 32], aa);
#pragma unroll
            for (int j = 0; j < KCP; j++) {
                float sm = 0.0f;
#pragma unroll
                for (int i = 0; i < 20; i++) sm += aa[i] * W0[i * 64 + kb + j];
                h[s][j] = siluN(sm) * 0.125f;
            }
        }

#pragma unroll 1
        for (int half = 0; half < 2; half++) {
            float os[4][8];
            fold_scalar_half4(h, lane, half, shN, shR, W1k, os);
#pragma unroll 1
            for (int c = 0; c < 2; c++) {
                __syncthreads();
#pragma unroll
                for (int f = 0; f < 4; f++)
#pragma unroll
                    for (int s = 0; s < 4; s++)
                        shS[warp * 4 * EPB + f * EPB + lane + s * 32] = os[s][c * 4 + f];
                __syncthreads();
                for (int i = tid; i < 4 * EPB; i += TBE) {
                    float sm = 0.0f;
#pragma unroll
                    for (int w = 0; w < NW; w++) sm += shS[w * 4 * EPB + i];
                    int e = i & (EPB - 1), f = i >> 7;
                    if (e0 + e < EI)
                        atomicAdd(&g_lig[(e0 + e) * NF + half * 8 + c * 4 + f], sm);
                }
            }
        }

#pragma unroll 1
        for (int half = 0; half < 2; half++) {
            float ov[4][12];
            fold_vector_half4(h, lane, half, shN, shR, W1k, ov);
#pragma unroll 1
            for (int c = 0; c < 3; c++) {
                __syncthreads();
#pragma unroll
                for (int f = 0; f < 4; f++)
#pragma unroll
                    for (int s = 0; s < 4; s++)
                        shS[warp * 4 * EPB + f * EPB + lane + s * 32] = ov[s][c * 4 + f];
                __syncthreads();
                for (int i = tid; i < 4 * EPB; i += TBE) {
                    float sm = 0.0f;
#pragma unroll
                    for (int w = 0; w < NW; w++) sm += shS[w * 4 * EPB + i];
                    int e = i & (EPB - 1), f = i >> 7;
                    if (e0 + e < EI)
                        atomicAdd(&g_lig[(e0 + e) * NF + 16 + half * 12 + c * 4 + f], sm);
                }
            }
        }
    }
}

// ---------------------------------------------------------------------------
// receptor TP readout (unchanged from R9): 128 edges/block, 4 slots/lane
// ---------------------------------------------------------------------------
__global__ void __launch_bounds__(TBE, 2) k_rec(
    const float* __restrict__ pos,
    const int* __restrict__ recI, const int* __restrict__ ligI, int EI,
    const float* __restrict__ W0, const float* __restrict__ W1,
    float* __restrict__ out)
{
    __shared__ float shL [NF * EPR];
    __shared__ float shRn[NF * EPR];
    __shared__ float shD [EPR];
    __shared__ int   shRi[EPR];

    int tid  = threadIdx.x;
    int lane = tid & 31;
    int warp = tid >> 5;
    int e0 = blockIdx.x * EPR;

    if (tid < EPR) {
        int e = min(e0 + tid, EI - 1);
        int ri = recI[e], li = ligI[e];
        shRi[tid] = ri;
        float vx = pos[li * 3 + 0] - pos[ri * 3 + 0];
        float vy = pos[li * 3 + 1] - pos[ri * 3 + 1];
        float vz = pos[li * 3 + 2] - pos[ri * 3 + 2];
        float d2 = vx * vx + vy * vy + vz * vz;
        shD[tid] = d2 * rsqrtf(d2);
    }
    __syncthreads();

    for (int i = tid; i < NF * EPR; i += TBE) {
        int e = i & (EPR - 1), f = i >> 7;
        int ec = min(e0 + e, EI - 1);
        shL [f * EPR + e] = g_lig[ec * NF + f];
        shRn[f * EPR + e] = g_node[shRi[e] * NF + f];
    }

    float h[4][KC];
    {
        int kb = warp * KC;
#pragma unroll 1
        for (int s = 0; s < 4; s++) {
            float aa[20];
            demb_compute(shD[lane + s * 32], aa);
#pragma unroll
            for (int j = 0; j < KC; j++) {
                float sm = 0.0f;
#pragma unroll
                for (int i = 0; i < 20; i++) sm += aa[i] * W0[i * 64 + kb + j];
                h[s][j] = siluN(sm) * 0.125f;
            }
        }
    }
    __syncthreads();

    float acc[4][8];
#pragma unroll
    for (int s = 0; s < 4; s++)
#pragma unroll
        for (int t = 0; t < 8; t++) acc[s][t] = 0.0f;
    const float* Wk = W1 + warp * KC * 2560;

    // scalar x scalar -> 8x0e
#pragma unroll 1
    for (int u = 0; u < 16; u++) {
        float lu[4];
#pragma unroll
        for (int s = 0; s < 4; s++) lu[s] = shL[u * EPR + lane + s * 32];
#pragma unroll 1
        for (int v = 0; v < 16; v++) {
            float cf[4];
#pragma unroll
            for (int s = 0; s < 4; s++) cf[s] = lu[s] * shRn[v * EPR + lane + s * 32];
            const float* base = Wk + (u * 16 + v) * 8;
#pragma unroll
            for (int j = 0; j < KC; j++) {
                float p[4];
#pragma unroll
                for (int s = 0; s < 4; s++) p[s] = cf[s] * h[s][j];
                const float4* bp = reinterpret_cast<const float4*>(base + j * 2560);
                float4 q0 = __ldg(bp), q1 = __ldg(bp + 1);
#pragma unroll
                for (int s = 0; s < 4; s++) {
                    acc[s][0] += p[s] * q0.x; acc[s][1] += p[s] * q0.y;
                    acc[s][2] += p[s] * q0.z; acc[s][3] += p[s] * q0.w;
                    acc[s][4] += p[s] * q1.x; acc[s][5] += p[s] * q1.y;
                    acc[s][6] += p[s] * q1.z; acc[s][7] += p[s] * q1.w;
                }
            }
        }
    }

    // vector x vector -> 8x0e
#pragma unroll 1
    for (int u = 0; u < 8; u++) {
        float la0[4], la1[4], la2[4];
#pragma unroll
        for (int s = 0; s < 4; s++) {
            int idx = lane + s * 32;
            la0[s] = shL[(16 + u * 3) * EPR + idx];
            la1[s] = shL[(17 + u * 3) * EPR + idx];
            la2[s] = shL[(18 + u * 3) * EPR + idx];
        }
#pragma unroll 1
        for (int v = 0; v < 8; v++) {
            float cf[4];
#pragma unroll
            for (int s = 0; s < 4; s++) {
                int idx = lane + s * 32;
                cf[s] = (la0[s] * shRn[(16 + v * 3) * EPR + idx] +
                         la1[s] * shRn[(17 + v * 3) * EPR + idx] +
                         la2[s] * shRn[(18 + v * 3) * EPR + idx]) * INVS3;
            }
            const float* base = Wk + 2048 + (u * 8 + v) * 8;
#pragma unroll
            for (int j = 0; j < KC; j++) {
                float p[4];
#pragma unroll
                for (int s = 0; s < 4; s++) p[s] = cf[s] * h[s][j];
                const float4* bp = reinterpret_cast<const float4*>(base + j * 2560);
                float4 q0 = __ldg(bp), q1 = __ldg(bp + 1);
#pragma unroll
                for (int s = 0; s < 4; s++) {
                    acc[s][0] += p[s] * q0.x; acc[s][1] += p[s] * q0.y;
                    acc[s][2] += p[s] * q0.z; acc[s][3] += p[s] * q0.w;
                    acc[s][4] += p[s] * q1.x; acc[s][5] += p[s] * q1.y;
                    acc[s][6] += p[s] * q1.z; acc[s][7] += p[s] * q1.w;
                }
            }
        }
    }

#pragma unroll
    for (int s = 0; s < 4; s++) {
        int e = e0 + lane + s * 32;
        if (e < EI) {
#pragma unroll
            for (int t = 0; t < 8; t++)
                atomicAdd(&out[e * 8 + t], PWREC * acc[s][t]);
        }
    }
}

// ---------------------------------------------------------------------------
// host launcher (graph-capturable: kernel launches only)
// ---------------------------------------------------------------------------
extern "C" void kernel_launch(void* const* d_in, const int* in_sizes, int n_in,
                              void* d_out, int out_size) {
    (void)n_in; (void)out_size;
    const float* x       = (const float*)d_in[0];
    const float* pos     = (const float*)d_in[1];
    const int*   eidx    = (const int*)  d_in[2];
    const float* eattr   = (const float*)d_in[3];
    const int*   iidx    = (const int*)  d_in[4];
    const float* emb_w0  = (const float*)d_in[5];
    const float* emb_w1  = (const float*)d_in[6];
    const float* imp0    = (const float*)d_in[7];
    const float* msg0_w0 = (const float*)d_in[8];
    const float* msg0_w1 = (const float*)d_in[9];
    const float* upd0_w0 = (const float*)d_in[10];
    const float* upd0_w1 = (const float*)d_in[11];
    const float* imp1    = (const float*)d_in[12];
    const float* msg1_w0 = (const float*)d_in[13];
    const float* msg1_w1 = (const float*)d_in[14];
    const float* upd1_w0 = (const float*)d_in[15];
    const float* upd1_w1 = (const float*)d_in[16];
    const float* lig_w0  = (const float*)d_in[17];
    const float* lig_w1  = (const float*)d_in[18];
    const float* rec_w0  = (const float*)d_in[19];
    const float* rec_w1  = (const float*)d_in[20];

    int N  = in_sizes[1] / 3;
    int A  = in_sizes[0] / N;
    int E  = in_sizes[2] / 2;
    int B  = in_sizes[3] / E;
    int EI = in_sizes[4] / 2;
    const int* src  = eidx;
    const int* dst  = eidx + E;
    const int* recI = iidx;
    const int* ligI = iidx + EI;
    float degf = (float)E / (float)N;

    int gn = (N + 127) / 128;
    int ge = (E + EPB - 1) / EPB;
    int gi = (EI + EPB - 1) / EPB;
    int gr = (EI + EPR - 1) / EPR;

    k_embed<<<gn, 128>>>(x, N, A, emb_w0, emb_w1);      // also zeroes g_msgs

    k_msg<<<ge, TBE>>>(pos, src, dst, eattr, E, B, msg0_w0, msg0_w1);
    k_update<<<gn, 128>>>(N, imp0, degf, upd0_w0, upd0_w1, 1.0f);  // re-zeroes g_msgs

    k_msg<<<ge, TBE>>>(pos, src, dst, eattr, E, B, msg1_w0, msg1_w1);
    k_update<<<gn, 128>>>(N, imp1, degf, upd1_w0, upd1_w1, 0.5f);

    k_lig<<<gi, TBE>>>(pos, recI, ligI, EI, lig_w0, lig_w1, (float*)d_out);  // zeroes d_out + g_lig
    k_rec<<<gr, TBE>>>(pos, recI, ligI, EI, rec_w0, rec_w1, (float*)d_out);
}

// round 14
// speedup vs baseline: 1.3124x; 1.3124x over previous
#include <cuda_runtime.h>
#include <math.h>

// ---------------------------------------------------------------------------
// InteractionPredictor: e3nn-style equivariant GNN, fully fused fp32.
// R13 = R9 (best known: k_msg/k_lig 64 edges/256thr, 2-slot fold, slice
// reduction; k_rec 128 edges, 4-slot) with two scheduling/latency fixes:
//  - k_rec splits K across gridDim.y=2 (KCR=4/warp) to kill the 1.06-wave
//    quantization tail (313 blocks @ 296 slots -> 626 @ 2.1 waves).
//  - k_embed/k_update use float4 weight loads + 64-thread blocks (they were
//    latency-bound at occ ~6% with scalar uniform LDGs).
// ---------------------------------------------------------------------------

#define TBE    256         /* threads per edge block      */
#define EPB    64          /* edges per block (msg/lig)   */
#define EPR    128         /* edges per block (rec)       */
#define KC     8           /* k-chunk per warp (msg/lig)  */
#define KCR    4           /* k-chunk per warp (rec, y-split) */
#define NW     8           /* warps per block             */
#define NF     40
#define NMAX   16384
#define EIMAX  65536

__device__ float g_node[NMAX * NF];
__device__ float g_msgs[NMAX * NF];
__device__ float g_lig [EIMAX * NF];

#define C24    0.20412414523193154f   /* sqrt(1/24)  */
#define C24S3  0.35355339059327373f   /* sqrt(1/8)   */
#define INVS3  0.57735026918962576f   /* 1/sqrt(3)   */
#define PWREC  0.05590169943749474f   /* 1/sqrt(320) */
#define DEMBC  8.4335731f             /* 1.14136*e^2 */
#define INV32  0.17677669529663687f   /* 1/sqrt(32)  */

__device__ __forceinline__ float siluN(float x) {
    return x * (1.0f / (1.0f + __expf(-x))) * 1.6789717f;
}

// ---------------------------------------------------------------------------
// node embedding (float4 weight loads); also zeroes g_msgs rows
// ---------------------------------------------------------------------------
__global__ void __launch_bounds__(64) k_embed(
    const float* __restrict__ x, int N, int A,
    const float* __restrict__ W0, const float* __restrict__ W1) {
    int n = blockIdx.x * blockDim.x + threadIdx.x;
    if (n >= N) return;
    float inv = rsqrtf((float)A);
    float a[16];
#pragma unroll
    for (int b = 0; b < 16; b++) a[b] = (b < A) ? x[n * A + b] : 0.0f;
    float h[64];
#pragma unroll 4
    for (int kq = 0; kq < 16; kq++) {
        float s0 = 0.0f, s1 = 0.0f, s2 = 0.0f, s3 = 0.0f;
#pragma unroll
        for (int b = 0; b < 16; b++)
            if (b < A) {
                float4 w = __ldg(reinterpret_cast<const float4*>(W0 + b * 64 + kq * 4));
                s0 += a[b] * w.x; s1 += a[b] * w.y; s2 += a[b] * w.z; s3 += a[b] * w.w;
            }
        h[kq * 4 + 0] = siluN(s0 * inv) * 0.125f;
        h[kq * 4 + 1] = siluN(s1 * inv) * 0.125f;
        h[kq * 4 + 2] = siluN(s2 * inv) * 0.125f;
        h[kq * 4 + 3] = siluN(s3 * inv) * 0.125f;
    }
    float* nr = g_node + n * NF;
#pragma unroll
    for (int wq = 0; wq < 4; wq++) {
        float s0 = 0.0f, s1 = 0.0f, s2 = 0.0f, s3 = 0.0f;
#pragma unroll 8
        for (int k = 0; k < 64; k++) {
            float4 w = __ldg(reinterpret_cast<const float4*>(W1 + k * 16 + wq * 4));
            float hk = h[k];
            s0 += hk * w.x; s1 += hk * w.y; s2 += hk * w.z; s3 += hk * w.w;
        }
        nr[wq * 4 + 0] = s0; nr[wq * 4 + 1] = s1;
        nr[wq * 4 + 2] = s2; nr[wq * 4 + 3] = s3;
    }
#pragma unroll
    for (int t = 0; t < 24; t++) nr[16 + t] = 0.0f;
    float* mr = g_msgs + n * NF;
#pragma unroll
    for (int t = 0; t < NF; t++) mr[t] = 0.0f;
}

// ---------------------------------------------------------------------------
// node update (float4 weight loads); re-zeroes msg row after consuming
// ---------------------------------------------------------------------------
__global__ void __launch_bounds__(64) k_update(
    int N, const float* __restrict__ imp, float degf,
    const float* __restrict__ W0, const float* __restrict__ W1, float gmul) {
    int n = blockIdx.x * blockDim.x + threadIdx.x;
    if (n >= N) return;
    float scale = imp[0] * rsqrtf(degf);
    float* nr = g_node + n * NF;
    float* mr = g_msgs + n * NF;
    float a[32];
#pragma unroll
    for (int t = 0; t < 16; t++) a[t] = mr[t] * scale;
#pragma unroll
    for (int t = 0; t < 16; t++) a[16 + t] = nr[t];
    float ge[24];
#pragma unroll
    for (int t = 0; t < 24; t++) ge[t] = (mr[16 + t] * scale + nr[16 + t]) * gmul;
#pragma unroll
    for (int t = 0; t < NF; t++) mr[t] = 0.0f;
    float h[64];
#pragma unroll 2
    for (int kq = 0; kq < 16; kq++) {
        float s0 = 0.0f, s1 = 0.0f, s2 = 0.0f, s3 = 0.0f;
#pragma unroll
        for (int b = 0; b < 32; b++) {
            float4 w = __ldg(reinterpret_cast<const float4*>(W0 + b * 64 + kq * 4));
            float ab = a[b];
            s0 += ab * w.x; s1 += ab * w.y; s2 += ab * w.z; s3 += ab * w.w;
        }
        h[kq * 4 + 0] = siluN(s0 * INV32) * 0.125f;
        h[kq * 4 + 1] = siluN(s1 * INV32) * 0.125f;
        h[kq * 4 + 2] = siluN(s2 * INV32) * 0.125f;
        h[kq * 4 + 3] = siluN(s3 * INV32) * 0.125f;
    }
    float sc[16];
#pragma unroll
    for (int wq = 0; wq < 4; wq++) {
        float s0 = 0.0f, s1 = 0.0f, s2 = 0.0f, s3 = 0.0f;
#pragma unroll 8
        for (int k = 0; k < 64; k++) {
            float4 w = __ldg(reinterpret_cast<const float4*>(W1 + k * 16 + wq * 4));
            float hk = h[k];
            s0 += hk * w.x; s1 += hk * w.y; s2 += hk * w.z; s3 += hk * w.w;
        }
        sc[wq * 4 + 0] = s0; sc[wq * 4 + 1] = s1;
        sc[wq * 4 + 2] = s2; sc[wq * 4 + 3] = s3;
    }
#pragma unroll
    for (int w = 0; w < 16; w++) nr[w] = sc[w];
#pragma unroll
    for (int t = 0; t < 24; t++) nr[16 + t] = ge[t];
}

// ---------------------------------------------------------------------------
__device__ __forceinline__ void demb_compute(float d, float* a) {
    float tt = d * 4.2f;
#pragma unroll
    for (int i = 0; i < 20; i++) {
        float diff = tt - (float)(i + 1);
        float p = diff + 1.0f, q = 1.0f - diff;
        float s1 = (p > 0.0f) ? __expf(-1.0f / p) : 0.0f;
        float s2 = (q > 0.0f) ? __expf(-1.0f / q) : 0.0f;
        a[i] = DEMBC * s1 * s2;
    }
}

// ---------------------------------------------------------------------------
// Scalar-output fold (blocks A+B -> 16 features); 2 edge-slots; R9 form.
// ---------------------------------------------------------------------------
__device__ __forceinline__ void fold_scalar(
    const float* __restrict__ ha, const float* __restrict__ hb, int lane,
    const float* __restrict__ shN, const float* __restrict__ shR,
    const float* __restrict__ W1k, float* __restrict__ slice)
{
    float ra0 = shR[lane],      ra1 = shR[EPB + lane],      ra2 = shR[2 * EPB + lane];
    float rb0 = shR[lane + 32], rb1 = shR[EPB + lane + 32], rb2 = shR[2 * EPB + lane + 32];

    float osA[16], osB[16];
#pragma unroll
    for (int t = 0; t < 16; t++) { osA[t] = 0.0f; osB[t] = 0.0f; }

    // Block A: 0e x 0e -> 0e ; cols [u*16, +16), u<16
#pragma unroll 1
    for (int u = 0; u < 16; u++) {
        float wa[16], wb[16];
#pragma unroll
        for (int t = 0; t < 16; t++) { wa[t] = 0.0f; wb[t] = 0.0f; }
        const float* base = W1k + u * 16;
#pragma unroll
        for (int j = 0; j < KC; j++) {
            const float4* p = reinterpret_cast<const float4*>(base + j * 576);
            float4 q0 = __ldg(p), q1 = __ldg(p + 1), q2 = __ldg(p + 2), q3 = __ldg(p + 3);
            float A = ha[j], Bv = hb[j];
            wa[0]+=A*q0.x; wa[1]+=A*q0.y; wa[2]+=A*q0.z; wa[3]+=A*q0.w;
            wa[4]+=A*q1.x; wa[5]+=A*q1.y; wa[6]+=A*q1.z; wa[7]+=A*q1.w;
            wa[8]+=A*q2.x; wa[9]+=A*q2.y; wa[10]+=A*q2.z; wa[11]+=A*q2.w;
            wa[12]+=A*q3.x; wa[13]+=A*q3.y; wa[14]+=A*q3.z; wa[15]+=A*q3.w;
            wb[0]+=Bv*q0.x; wb[1]+=Bv*q0.y; wb[2]+=Bv*q0.z; wb[3]+=Bv*q0.w;
            wb[4]+=Bv*q1.x; wb[5]+=Bv*q1.y; wb[6]+=Bv*q1.z; wb[7]+=Bv*q1.w;
            wb[8]+=Bv*q2.x; wb[9]+=Bv*q2.y; wb[10]+=Bv*q2.z; wb[11]+=Bv*q2.w;
            wb[12]+=Bv*q3.x; wb[13]+=Bv*q3.y; wb[14]+=Bv*q3.z; wb[15]+=Bv*q3.w;
        }
        float cfa = C24 * shN[u * EPB + lane];
        float cfb = C24 * shN[u * EPB + lane + 32];
#pragma unroll
        for (int t = 0; t < 16; t++) { osA[t] += cfa * wa[t]; osB[t] += cfb * wb[t]; }
    }

    // Block B: 1o x 1o -> 0e ; cols [256+u*16), u<8 ; coef C24*(xv_u . r)
#pragma unroll 1
    for (int u = 0; u < 8; u++) {
        float wa[16], wb[16];
#pragma unroll
        for (int t = 0; t < 16; t++) { wa[t] = 0.0f; wb[t] = 0.0f; }
        const float* base = W1k + 256 + u * 16;
#pragma unroll
        for (int j = 0; j < KC; j++) {
            const float4* p = reinterpret_cast<const float4*>(base + j * 576);
            float4 q0 = __ldg(p), q1 = __ldg(p + 1), q2 = __ldg(p + 2), q3 = __ldg(p + 3);
            float A = ha[j], Bv = hb[j];
            wa[0]+=A*q0.x; wa[1]+=A*q0.y; wa[2]+=A*q0.z; wa[3]+=A*q0.w;
            wa[4]+=A*q1.x; wa[5]+=A*q1.y; wa[6]+=A*q1.z; wa[7]+=A*q1.w;
            wa[8]+=A*q2.x; wa[9]+=A*q2.y; wa[10]+=A*q2.z; wa[11]+=A*q2.w;
            wa[12]+=A*q3.x; wa[13]+=A*q3.y; wa[14]+=A*q3.z; wa[15]+=A*q3.w;
            wb[0]+=Bv*q0.x; wb[1]+=Bv*q0.y; wb[2]+=Bv*q0.z; wb[3]+=Bv*q0.w;
            wb[4]+=Bv*q1.x; wb[5]+=Bv*q1.y; wb[6]+=Bv*q1.z; wb[7]+=Bv*q1.w;
            wb[8]+=Bv*q2.x; wb[9]+=Bv*q2.y; wb[10]+=Bv*q2.z; wb[11]+=Bv*q2.w;
            wb[12]+=Bv*q3.x; wb[13]+=Bv*q3.y; wb[14]+=Bv*q3.z; wb[15]+=Bv*q3.w;
        }
        float cfa = C24 * (shN[(16 + u * 3) * EPB + lane] * ra0 +
                           shN[(17 + u * 3) * EPB + lane] * ra1 +
                           shN[(18 + u * 3) * EPB + lane] * ra2);
        float cfb = C24 * (shN[(16 + u * 3) * EPB + lane + 32] * rb0 +
                           shN[(17 + u * 3) * EPB + lane + 32] * rb1 +
                           shN[(18 + u * 3) * EPB + lane + 32] * rb2);
#pragma unroll
        for (int t = 0; t < 16; t++) { osA[t] += cfa * wa[t]; osB[t] += cfb * wb[t]; }
    }

#pragma unroll
    for (int t = 0; t < 16; t++) {
        slice[t * EPB + lane]      = osA[t];
        slice[t * EPB + lane + 32] = osB[t];
    }
}

// ---------------------------------------------------------------------------
// Vector-output fold, one half (4 of the 8 vector mults -> 12 features).
// ---------------------------------------------------------------------------
__device__ __forceinline__ void fold_vector_half(
    const float* __restrict__ ha, const float* __restrict__ hb, int lane,
    const float* __restrict__ shN, const float* __restrict__ shR, int half,
    const float* __restrict__ W1k, float* __restrict__ slice)
{
    float ra0 = shR[lane],      ra1 = shR[EPB + lane],      ra2 = shR[2 * EPB + lane];
    float rb0 = shR[lane + 32], rb1 = shR[EPB + lane + 32], rb2 = shR[2 * EPB + lane + 32];

    float ovA[12], ovB[12];
#pragma unroll
    for (int t = 0; t < 12; t++) { ovA[t] = 0.0f; ovB[t] = 0.0f; }

    // Block C: 0e x 1o -> 1o ; cols [384 + u*8 + half*4), u<16
#pragma unroll 1
    for (int u = 0; u < 16; u++) {
        float wa[4], wb[4];
#pragma unroll
        for (int t = 0; t < 4; t++) { wa[t] = 0.0f; wb[t] = 0.0f; }
        const float* base = W1k + 384 + u * 8 + half * 4;
#pragma unroll
        for (int j = 0; j < KC; j++) {
            float4 q = __ldg(reinterpret_cast<const float4*>(base + j * 576));
            float A = ha[j], Bv = hb[j];
            wa[0]+=A*q.x; wa[1]+=A*q.y; wa[2]+=A*q.z; wa[3]+=A*q.w;
            wb[0]+=Bv*q.x; wb[1]+=Bv*q.y; wb[2]+=Bv*q.z; wb[3]+=Bv*q.w;
        }
        float cfa = C24S3 * shN[u * EPB + lane];
        float cfb = C24S3 * shN[u * EPB + lane + 32];
#pragma unroll
        for (int t = 0; t < 4; t++) {
            float sa = cfa * wa[t], sb = cfb * wb[t];
            ovA[t*3+0] += sa * ra0; ovA[t*3+1] += sa * ra1; ovA[t*3+2] += sa * ra2;
            ovB[t*3+0] += sb * rb0; ovB[t*3+1] += sb * rb1; ovB[t*3+2] += sb * rb2;
        }
    }

    // Block D: 1o x 0e -> 1o ; cols [512 + u*8 + half*4), u<8
#pragma unroll 1
    for (int u = 0; u < 8; u++) {
        float wa[4], wb[4];
#pragma unroll
        for (int t = 0; t < 4; t++) { wa[t] = 0.0f; wb[t] = 0.0f; }
        const float* base = W1k + 512 + u * 8 + half * 4;
#pragma unroll
        for (int j = 0; j < KC; j++) {
            float4 q = __ldg(reinterpret_cast<const float4*>(base + j * 576));
            float A = ha[j], Bv = hb[j];
            wa[0]+=A*q.x; wa[1]+=A*q.y; wa[2]+=A*q.z; wa[3]+=A*q.w;
            wb[0]+=Bv*q.x; wb[1]+=Bv*q.y; wb[2]+=Bv*q.z; wb[3]+=Bv*q.w;
        }
        float ca0 = C24 * shN[(16 + u * 3) * EPB + lane];
        float ca1 = C24 * shN[(17 + u * 3) * EPB + lane];
        float ca2 = C24 * shN[(18 + u * 3) * EPB + lane];
        float cb0 = C24 * shN[(16 + u * 3) * EPB + lane + 32];
        float cb1 = C24 * shN[(17 + u * 3) * EPB + lane + 32];
        float cb2 = C24 * shN[(18 + u * 3) * EPB + lane + 32];
#pragma unroll
        for (int t = 0; t < 4; t++) {
            ovA[t*3+0] += ca0 * wa[t]; ovA[t*3+1] += ca1 * wa[t]; ovA[t*3+2] += ca2 * wa[t];
            ovB[t*3+0] += cb0 * wb[t]; ovB[t*3+1] += cb1 * wb[t]; ovB[t*3+2] += cb2 * wb[t];
        }
    }

#pragma unroll
    for (int t = 0; t < 12; t++) {
        slice[t * EPB + lane]      = ovA[t];
        slice[t * EPB + lane + 32] = ovB[t];
    }
}

// ---------------------------------------------------------------------------
// message kernel: 64 edges / 256 threads, 8 warps x KC=8, slice reduction
// ---------------------------------------------------------------------------
__global__ void __launch_bounds__(TBE, 2) k_msg(
    const float* __restrict__ pos,
    const int* __restrict__ srcI, const int* __restrict__ dstI,
    const float* __restrict__ eattr, int E, int B,
    const float* __restrict__ W0, const float* __restrict__ W1)
{
    __shared__ float shN[NF * EPB];          // 10 KB
    __shared__ float shS[NW * 16 * EPB];     // 32 KB
    __shared__ float shR[3 * EPB];
    __shared__ int   shSi[EPB];
    __shared__ int   shDi[EPB];

    int tid  = threadIdx.x;
    int lane = tid & 31;
    int warp = tid >> 5;
    int e0 = blockIdx.x * EPB;

    if (tid < EPB) {
        int e = min(e0 + tid, E - 1);
        int si = srcI[e], di = dstI[e];
        shSi[tid] = si; shDi[tid] = di;
        float vx = pos[di * 3 + 0] - pos[si * 3 + 0];
        float vy = pos[di * 3 + 1] - pos[si * 3 + 1];
        float vz = pos[di * 3 + 2] - pos[si * 3 + 2];
        float rn = rsqrtf(vx * vx + vy * vy + vz * vz);
        shR[tid]           = vx * rn;
        shR[EPB + tid]     = vy * rn;
        shR[2 * EPB + tid] = vz * rn;
    }
    __syncthreads();

    for (int i = tid; i < NF * EPB; i += TBE) {
        int e = i & (EPB - 1), f = i >> 6;
        shN[f * EPB + e] = g_node[shSi[e] * NF + f];
    }

    float ha[KC], hb[KC];
    {
        float inv = rsqrtf((float)B);
        int kb = warp * KC;
        int ea = min(e0 + lane, E - 1);
        int eb = min(e0 + lane + 32, E - 1);
        float aa[8], ab[8];
#pragma unroll
        for (int b = 0; b < 8; b++) {
            aa[b] = (b < B) ? eattr[ea * B + b] : 0.0f;
            ab[b] = (b < B) ? eattr[eb * B + b] : 0.0f;
        }
#pragma unroll
        for (int j = 0; j < KC; j++) {
            float sa = 0.0f, sb = 0.0f;
#pragma unroll
            for (int b = 0; b < 8; b++)
                if (b < B) {
                    float w = W0[b * 64 + kb + j];
                    sa += aa[b] * w; sb += ab[b] * w;
                }
            ha[j] = siluN(sa * inv) * 0.125f;
            hb[j] = siluN(sb * inv) * 0.125f;
        }
    }
    __syncthreads();

    const float* W1k = W1 + warp * KC * 576;

    // ---- scalar phase ----
    fold_scalar(ha, hb, lane, shN, shR, W1k, shS + warp * 16 * EPB);
    __syncthreads();
    for (int i = tid; i < 16 * EPB; i += TBE) {
        float s = 0.0f;
#pragma unroll
        for (int w = 0; w < NW; w++) s += shS[w * 16 * EPB + i];
        int e = i & (EPB - 1), f = i >> 6;
        if (e0 + e < E) atomicAdd(&g_msgs[shDi[e] * NF + f], s);
    }
    __syncthreads();

    // ---- vector phases (2 halves of 12 features) ----
#pragma unroll 1
    for (int half = 0; half < 2; half++) {
        fold_vector_half(ha, hb, lane, shN, shR, half, W1k, shS + warp * 12 * EPB);
        __syncthreads();
        for (int i = tid; i < 12 * EPB; i += TBE) {
            float s = 0.0f;
#pragma unroll
            for (int w = 0; w < NW; w++) s += shS[w * 12 * EPB + i];
            int e = i & (EPB - 1), f = i >> 6;
            if (e0 + e < E) atomicAdd(&g_msgs[shDi[e] * NF + 16 + half * 12 + f], s);
        }
        __syncthreads();
    }
}

// ---------------------------------------------------------------------------
// ligand embedding; also zeroes d_out rows for k_rec's atomic reduction
// ---------------------------------------------------------------------------
__global__ void __launch_bounds__(TBE, 2) k_lig(
    const float* __restrict__ pos,
    const int* __restrict__ recI, const int* __restrict__ ligI, int EI,
    const float* __restrict__ W0, const float* __restrict__ W1,
    float* __restrict__ out)
{
    __shared__ float shN[NF * EPB];
    __shared__ float shS[NW * 16 * EPB];
    __shared__ float shR[3 * EPB];
    __shared__ float shD[EPB];
    __shared__ int   shLi[EPB];

    int tid  = threadIdx.x;
    int lane = tid & 31;
    int warp = tid >> 5;
    int e0 = blockIdx.x * EPB;

    // zero this block's output rows (k_rec accumulates atomically)
    for (int i = tid; i < 8 * EPB; i += TBE) {
        int e = i >> 3;
        if (e0 + e < EI) out[(e0 + e) * 8 + (i & 7)] = 0.0f;
    }

    if (tid < EPB) {
        int e = min(e0 + tid, EI - 1);
        int ri = recI[e], li = ligI[e];
        shLi[tid] = li;
        float vx = pos[li * 3 + 0] - pos[ri * 3 + 0];
        float vy = pos[li * 3 + 1] - pos[ri * 3 + 1];
        float vz = pos[li * 3 + 2] - pos[ri * 3 + 2];
        float d2 = vx * vx + vy * vy + vz * vz;
        float invd = rsqrtf(d2);
        shR[tid]           = vx * invd;
        shR[EPB + tid]     = vy * invd;
        shR[2 * EPB + tid] = vz * invd;
        shD[tid]           = d2 * invd;
    }
    __syncthreads();

    for (int i = tid; i < NF * EPB; i += TBE) {
        int e = i & (EPB - 1), f = i >> 6;
        shN[f * EPB + e] = g_node[shLi[e] * NF + f];
    }

    float ha[KC], hb[KC];
    {
        int kb = warp * KC;
        float aa[20], ab[20];
        demb_compute(shD[lane],      aa);
        demb_compute(shD[lane + 32], ab);
#pragma unroll
        for (int j = 0; j < KC; j++) {
            float sa = 0.0f, sb = 0.0f;
#pragma unroll
            for (int i = 0; i < 20; i++) {
                float w = W0[i * 64 + kb + j];
                sa += aa[i] * w; sb += ab[i] * w;
            }
            ha[j] = siluN(sa) * 0.125f;
            hb[j] = siluN(sb) * 0.125f;
        }
    }
    __syncthreads();

    const float* W1k = W1 + warp * KC * 576;

    fold_scalar(ha, hb, lane, shN, shR, W1k, shS + warp * 16 * EPB);
    __syncthreads();
    for (int i = tid; i < 16 * EPB; i += TBE) {
        float s = 0.0f;
#pragma unroll
        for (int w = 0; w < NW; w++) s += shS[w * 16 * EPB + i];
        int e = i & (EPB - 1), f = i >> 6;
        if (e0 + e < EI) g_lig[(e0 + e) * NF + f] = s;
    }
    __syncthreads();

#pragma unroll 1
    for (int half = 0; half < 2; half++) {
        fold_vector_half(ha, hb, lane, shN, shR, half, W1k, shS + warp * 12 * EPB);
        __syncthreads();
        for (int i = tid; i < 12 * EPB; i += TBE) {
            float s = 0.0f;
#pragma unroll
            for (int w = 0; w < NW; w++) s += shS[w * 12 * EPB + i];
            int e = i & (EPB - 1), f = i >> 6;
            if (e0 + e < EI) g_lig[(e0 + e) * NF + 16 + half * 12 + f] = s;
        }
        __syncthreads();
    }
}

// ---------------------------------------------------------------------------
// receptor TP readout: 128 edges/block, 4 edge-slots/lane, K split across
// gridDim.y=2 (each y-block covers 32 hidden units: kb = warp*4 + y*32).
// Partials accumulate atomically into d_out (pre-zeroed by k_lig).
// ---------------------------------------------------------------------------
__global__ void __launch_bounds__(TBE, 2) k_rec(
    const float* __restrict__ pos,
    const int* __restrict__ recI, const int* __restrict__ ligI, int EI,
    const float* __restrict__ W0, const float* __restrict__ W1,
    float* __restrict__ out)
{
    __shared__ float shL [NF * EPR];
    __shared__ float shRn[NF * EPR];
    __shared__ float shD [EPR];
    __shared__ int   shRi[EPR];

    int tid  = threadIdx.x;
    int lane = tid & 31;
    int warp = tid >> 5;
    int e0 = blockIdx.x * EPR;
    int kb = warp * KCR + blockIdx.y * 32;

    if (tid < EPR) {
        int e = min(e0 + tid, EI - 1);
        int ri = recI[e], li = ligI[e];
        shRi[tid] = ri;
        float vx = pos[li * 3 + 0] - pos[ri * 3 + 0];
        float vy = pos[li * 3 + 1] - pos[ri * 3 + 1];
        float vz = pos[li * 3 + 2] - pos[ri * 3 + 2];
        float d2 = vx * vx + vy * vy + vz * vz;
        shD[tid] = d2 * rsqrtf(d2);
    }
    __syncthreads();

    for (int i = tid; i < NF * EPR; i += TBE) {
        int e = i & (EPR - 1), f = i >> 7;
        int ec = min(e0 + e, EI - 1);
        shL [f * EPR + e] = g_lig[ec * NF + f];
        shRn[f * EPR + e] = g_node[shRi[e] * NF + f];
    }

    float h[4][KCR];
    {
#pragma unroll 1
        for (int s = 0; s < 4; s++) {
            float aa[20];
            demb_compute(shD[lane + s * 32], aa);
#pragma unroll
            for (int j = 0; j < KCR; j++) {
                float sm = 0.0f;
#pragma unroll
                for (int i = 0; i < 20; i++) sm += aa[i] * W0[i * 64 + kb + j];
                h[s][j] = siluN(sm) * 0.125f;
            }
        }
    }
    __syncthreads();

    float acc[4][8];
#pragma unroll
    for (int s = 0; s < 4; s++)
#pragma unroll
        for (int t = 0; t < 8; t++) acc[s][t] = 0.0f;
    const float* Wk = W1 + kb * 2560;

    // scalar x scalar -> 8x0e
#pragma unroll 1
    for (int u = 0; u < 16; u++) {
        float lu[4];
#pragma unroll
        for (int s = 0; s < 4; s++) lu[s] = shL[u * EPR + lane + s * 32];
#pragma unroll 1
        for (int v = 0; v < 16; v++) {
            float cf[4];
#pragma unroll
            for (int s = 0; s < 4; s++) cf[s] = lu[s] * shRn[v * EPR + lane + s * 32];
            const float* base = Wk + (u * 16 + v) * 8;
#pragma unroll
            for (int j = 0; j < KCR; j++) {
                float p[4];
#pragma unroll
                for (int s = 0; s < 4; s++) p[s] = cf[s] * h[s][j];
                const float4* bp = reinterpret_cast<const float4*>(base + j * 2560);
                float4 q0 = __ldg(bp), q1 = __ldg(bp + 1);
#pragma unroll
                for (int s = 0; s < 4; s++) {
                    acc[s][0] += p[s] * q0.x; acc[s][1] += p[s] * q0.y;
                    acc[s][2] += p[s] * q0.z; acc[s][3] += p[s] * q0.w;
                    acc[s][4] += p[s] * q1.x; acc[s][5] += p[s] * q1.y;
                    acc[s][6] += p[s] * q1.z; acc[s][7] += p[s] * q1.w;
                }
            }
        }
    }

    // vector x vector -> 8x0e
#pragma unroll 1
    for (int u = 0; u < 8; u++) {
        float la0[4], la1[4], la2[4];
#pragma unroll
        for (int s = 0; s < 4; s++) {
            int idx = lane + s * 32;
            la0[s] = shL[(16 + u * 3) * EPR + idx];
            la1[s] = shL[(17 + u * 3) * EPR + idx];
            la2[s] = shL[(18 + u * 3) * EPR + idx];
        }
#pragma unroll 1
        for (int v = 0; v < 8; v++) {
            float cf[4];
#pragma unroll
            for (int s = 0; s < 4; s++) {
                int idx = lane + s * 32;
                cf[s] = (la0[s] * shRn[(16 + v * 3) * EPR + idx] +
                         la1[s] * shRn[(17 + v * 3) * EPR + idx] +
                         la2[s] * shRn[(18 + v * 3) * EPR + idx]) * INVS3;
            }
            const float* base = Wk + 2048 + (u * 8 + v) * 8;
#pragma unroll
            for (int j = 0; j < KCR; j++) {
                float p[4];
#pragma unroll
                for (int s = 0; s < 4; s++) p[s] = cf[s] * h[s][j];
                const float4* bp = reinterpret_cast<const float4*>(base + j * 2560);
                float4 q0 = __ldg(bp), q1 = __ldg(bp + 1);
#pragma unroll
                for (int s = 0; s < 4; s++) {
                    acc[s][0] += p[s] * q0.x; acc[s][1] += p[s] * q0.y;
                    acc[s][2] += p[s] * q0.z; acc[s][3] += p[s] * q0.w;
                    acc[s][4] += p[s] * q1.x; acc[s][5] += p[s] * q1.y;
                    acc[s][6] += p[s] * q1.z; acc[s][7] += p[s] * q1.w;
                }
            }
        }
    }

#pragma unroll
    for (int s = 0; s < 4; s++) {
        int e = e0 + lane + s * 32;
        if (e < EI) {
#pragma unroll
            for (int t = 0; t < 8; t++)
                atomicAdd(&out[e * 8 + t], PWREC * acc[s][t]);
        }
    }
}

// ---------------------------------------------------------------------------
// host launcher (graph-capturable: kernel launches only)
// ---------------------------------------------------------------------------
extern "C" void kernel_launch(void* const* d_in, const int* in_sizes, int n_in,
                              void* d_out, int out_size) {
    (void)n_in; (void)out_size;
    const float* x       = (const float*)d_in[0];
    const float* pos     = (const float*)d_in[1];
    const int*   eidx    = (const int*)  d_in[2];
    const float* eattr   = (const float*)d_in[3];
    const int*   iidx    = (const int*)  d_in[4];
    const float* emb_w0  = (const float*)d_in[5];
    const float* emb_w1  = (const float*)d_in[6];
    const float* imp0    = (const float*)d_in[7];
    const float* msg0_w0 = (const float*)d_in[8];
    const float* msg0_w1 = (const float*)d_in[9];
    const float* upd0_w0 = (const float*)d_in[10];
    const float* upd0_w1 = (const float*)d_in[11];
    const float* imp1    = (const float*)d_in[12];
    const float* msg1_w0 = (const float*)d_in[13];
    const float* msg1_w1 = (const float*)d_in[14];
    const float* upd1_w0 = (const float*)d_in[15];
    const float* upd1_w1 = (const float*)d_in[16];
    const float* lig_w0  = (const float*)d_in[17];
    const float* lig_w1  = (const float*)d_in[18];
    const float* rec_w0  = (const float*)d_in[19];
    const float* rec_w1  = (const float*)d_in[20];

    int N  = in_sizes[1] / 3;
    int A  = in_sizes[0] / N;
    int E  = in_sizes[2] / 2;
    int B  = in_sizes[3] / E;
    int EI = in_sizes[4] / 2;
    const int* src  = eidx;
    const int* dst  = eidx + E;
    const int* recI = iidx;
    const int* ligI = iidx + EI;
    float degf = (float)E / (float)N;

    int gn = (N + 63) / 64;
    int ge = (E + EPB - 1) / EPB;
    int gi = (EI + EPB - 1) / EPB;
    dim3 gr((EI + EPR - 1) / EPR, 2);

    k_embed<<<gn, 64>>>(x, N, A, emb_w0, emb_w1);       // also zeroes g_msgs

    k_msg<<<ge, TBE>>>(pos, src, dst, eattr, E, B, msg0_w0, msg0_w1);
    k_update<<<gn, 64>>>(N, imp0, degf, upd0_w0, upd0_w1, 1.0f);   // re-zeroes g_msgs

    k_msg<<<ge, TBE>>>(pos, src, dst, eattr, E, B, msg1_w0, msg1_w1);
    k_update<<<gn, 64>>>(N, imp1, degf, upd1_w0, upd1_w1, 0.5f);

    k_lig<<<gi, TBE>>>(pos, recI, ligI, EI, lig_w0, lig_w1, (float*)d_out);  // zeroes d_out
    k_rec<<<gr, TBE>>>(pos, recI, ligI, EI, rec_w0, rec_w1, (float*)d_out);
}

// round 15
// speedup vs baseline: 1.3568x; 1.0339x over previous
#include <cuda_runtime.h>
#include <math.h>

// ---------------------------------------------------------------------------
// InteractionPredictor: e3nn-style equivariant GNN, fully fused fp32.
// R14 = R13 with k_msg/k_lig weight access restructured: W1 is staged into
// shared memory COALESCED (once per block, in slabs) and the fold reads
// uniform-broadcast LDS.128 instead of uniform LDG.128. This removes the
// 4x wavefront cost of broadcast global loads that made k_msg L1-bound.
// Fold math/structure identical to R9/R13 (64 edges, 8 warps x KC=8,
// 2 edge-slots/lane, slice reduction). k_rec/k_embed/k_update from R13.
// ---------------------------------------------------------------------------

#define TBE    256         /* threads per edge block      */
#define EPB    64          /* edges per block (msg/lig)   */
#define EPR    128         /* edges per block (rec)       */
#define KC     8           /* k-chunk per warp (msg/lig)  */
#define KCR    4           /* k-chunk per warp (rec)      */
#define NW     8           /* warps per block             */
#define NF     40
#define SHS_F  9216        /* union buffer floats (36 KB) */

__device__ float g_node[16384 * NF];
__device__ float g_msgs[16384 * NF];
__device__ float g_lig [65536 * NF];

#define C24    0.20412414523193154f   /* sqrt(1/24)  */
#define C24S3  0.35355339059327373f   /* sqrt(1/8)   */
#define INVS3  0.57735026918962576f   /* 1/sqrt(3)   */
#define PWREC  0.05590169943749474f   /* 1/sqrt(320) */
#define DEMBC  8.4335731f             /* 1.14136*e^2 */
#define INV32  0.17677669529663687f   /* 1/sqrt(32)  */

__device__ __forceinline__ float siluN(float x) {
    return x * (1.0f / (1.0f + __expf(-x))) * 1.6789717f;
}

// ---------------------------------------------------------------------------
// node embedding (float4 weight loads); also zeroes g_msgs rows
// ---------------------------------------------------------------------------
__global__ void __launch_bounds__(64) k_embed(
    const float* __restrict__ x, int N, int A,
    const float* __restrict__ W0, const float* __restrict__ W1) {
    int n = blockIdx.x * blockDim.x + threadIdx.x;
    if (n >= N) return;
    float inv = rsqrtf((float)A);
    float a[16];
#pragma unroll
    for (int b = 0; b < 16; b++) a[b] = (b < A) ? x[n * A + b] : 0.0f;
    float h[64];
#pragma unroll 4
    for (int kq = 0; kq < 16; kq++) {
        float s0 = 0.0f, s1 = 0.0f, s2 = 0.0f, s3 = 0.0f;
#pragma unroll
        for (int b = 0; b < 16; b++)
            if (b < A) {
                float4 w = __ldg(reinterpret_cast<const float4*>(W0 + b * 64 + kq * 4));
                s0 += a[b] * w.x; s1 += a[b] * w.y; s2 += a[b] * w.z; s3 += a[b] * w.w;
            }
        h[kq * 4 + 0] = siluN(s0 * inv) * 0.125f;
        h[kq * 4 + 1] = siluN(s1 * inv) * 0.125f;
        h[kq * 4 + 2] = siluN(s2 * inv) * 0.125f;
        h[kq * 4 + 3] = siluN(s3 * inv) * 0.125f;
    }
    float* nr = g_node + n * NF;
#pragma unroll
    for (int wq = 0; wq < 4; wq++) {
        float s0 = 0.0f, s1 = 0.0f, s2 = 0.0f, s3 = 0.0f;
#pragma unroll 8
        for (int k = 0; k < 64; k++) {
            float4 w = __ldg(reinterpret_cast<const float4*>(W1 + k * 16 + wq * 4));
            float hk = h[k];
            s0 += hk * w.x; s1 += hk * w.y; s2 += hk * w.z; s3 += hk * w.w;
        }
        nr[wq * 4 + 0] = s0; nr[wq * 4 + 1] = s1;
        nr[wq * 4 + 2] = s2; nr[wq * 4 + 3] = s3;
    }
#pragma unroll
    for (int t = 0; t < 24; t++) nr[16 + t] = 0.0f;
    float* mr = g_msgs + n * NF;
#pragma unroll
    for (int t = 0; t < NF; t++) mr[t] = 0.0f;
}

// ---------------------------------------------------------------------------
// node update (float4 weight loads); re-zeroes msg row after consuming
// ---------------------------------------------------------------------------
__global__ void __launch_bounds__(64) k_update(
    int N, const float* __restrict__ imp, float degf,
    const float* __restrict__ W0, const float* __restrict__ W1, float gmul) {
    int n = blockIdx.x * blockDim.x + threadIdx.x;
    if (n >= N) return;
    float scale = imp[0] * rsqrtf(degf);
    float* nr = g_node + n * NF;
    float* mr = g_msgs + n * NF;
    float a[32];
#pragma unroll
    for (int t = 0; t < 16; t++) a[t] = mr[t] * scale;
#pragma unroll
    for (int t = 0; t < 16; t++) a[16 + t] = nr[t];
    float ge[24];
#pragma unroll
    for (int t = 0; t < 24; t++) ge[t] = (mr[16 + t] * scale + nr[16 + t]) * gmul;
#pragma unroll
    for (int t = 0; t < NF; t++) mr[t] = 0.0f;
    float h[64];
#pragma unroll 2
    for (int kq = 0; kq < 16; kq++) {
        float s0 = 0.0f, s1 = 0.0f, s2 = 0.0f, s3 = 0.0f;
#pragma unroll
        for (int b = 0; b < 32; b++) {
            float4 w = __ldg(reinterpret_cast<const float4*>(W0 + b * 64 + kq * 4));
            float ab = a[b];
            s0 += ab * w.x; s1 += ab * w.y; s2 += ab * w.z; s3 += ab * w.w;
        }
        h[kq * 4 + 0] = siluN(s0 * INV32) * 0.125f;
        h[kq * 4 + 1] = siluN(s1 * INV32) * 0.125f;
        h[kq * 4 + 2] = siluN(s2 * INV32) * 0.125f;
        h[kq * 4 + 3] = siluN(s3 * INV32) * 0.125f;
    }
    float sc[16];
#pragma unroll
    for (int wq = 0; wq < 4; wq++) {
        float s0 = 0.0f, s1 = 0.0f, s2 = 0.0f, s3 = 0.0f;
#pragma unroll 8
        for (int k = 0; k < 64; k++) {
            float4 w = __ldg(reinterpret_cast<const float4*>(W1 + k * 16 + wq * 4));
            float hk = h[k];
            s0 += hk * w.x; s1 += hk * w.y; s2 += hk * w.z; s3 += hk * w.w;
        }
        sc[wq * 4 + 0] = s0; sc[wq * 4 + 1] = s1;
        sc[wq * 4 + 2] = s2; sc[wq * 4 + 3] = s3;
    }
#pragma unroll
    for (int w = 0; w < 16; w++) nr[w] = sc[w];
#pragma unroll
    for (int t = 0; t < 24; t++) nr[16 + t] = ge[t];
}

// ---------------------------------------------------------------------------
__device__ __forceinline__ void demb_compute(float d, float* a) {
    float tt = d * 4.2f;
#pragma unroll
    for (int i = 0; i < 20; i++) {
        float diff = tt - (float)(i + 1);
        float p = diff + 1.0f, q = 1.0f - diff;
        float s1 = (p > 0.0f) ? __expf(-1.0f / p) : 0.0f;
        float s2 = (q > 0.0f) ? __expf(-1.0f / q) : 0.0f;
        a[i] = DEMBC * s1 * s2;
    }
}

// ---------------------------------------------------------------------------
// Shared edge-kernel body: smem-staged weights. Used by k_msg and k_lig.
// shS layout (floats, total SHS_F = 9216 = 36 KB):
//   scalar phase: slab rounds use [0, 4096); slices use [0, 8192)
//   vector phase: slab (C 4096 + D 2048) at [0, 6144); slices [6144, 9216)
// ---------------------------------------------------------------------------
struct EdgeCtx {
    const float* shN;   // node feats [40][EPB]
    const float* shR;   // unit vec [3][EPB]
    float* shS;
    int lane, warp, tid;
};

// fold one scalar round (4 u's of A or B) from the staged slab
__device__ __forceinline__ void fold_scalar_round(
    const EdgeCtx& c, const float* ha, const float* hb,
    int u0, int isB, float* osA, float* osB)
{
    int lane = c.lane;
#pragma unroll
    for (int uu = 0; uu < 4; uu++) {
        int u = u0 + uu;
        float cfa, cfb;
        if (!isB) {
            cfa = C24 * c.shN[u * EPB + lane];
            cfb = C24 * c.shN[u * EPB + lane + 32];
        } else {
            cfa = C24 * (c.shN[(16 + u * 3) * EPB + lane] * c.shR[lane] +
                         c.shN[(17 + u * 3) * EPB + lane] * c.shR[EPB + lane] +
                         c.shN[(18 + u * 3) * EPB + lane] * c.shR[2 * EPB + lane]);
            cfb = C24 * (c.shN[(16 + u * 3) * EPB + lane + 32] * c.shR[lane + 32] +
                         c.shN[(17 + u * 3) * EPB + lane + 32] * c.shR[EPB + lane + 32] +
                         c.shN[(18 + u * 3) * EPB + lane + 32] * c.shR[2 * EPB + lane + 32]);
        }
        float wa[16], wb[16];
#pragma unroll
        for (int t = 0; t < 16; t++) { wa[t] = 0.0f; wb[t] = 0.0f; }
#pragma unroll
        for (int j = 0; j < KC; j++) {
            // slab float4 layout: idx = (k*4 + uu)*4 + tq, k = warp*8+j
            const float4* p = reinterpret_cast<const float4*>(
                c.shS + (c.warp * KC + j) * 64 + uu * 16);
            float4 q0 = p[0], q1 = p[1], q2 = p[2], q3 = p[3];
            float A = ha[j], Bv = hb[j];
            wa[0]+=A*q0.x; wa[1]+=A*q0.y; wa[2]+=A*q0.z; wa[3]+=A*q0.w;
            wa[4]+=A*q1.x; wa[5]+=A*q1.y; wa[6]+=A*q1.z; wa[7]+=A*q1.w;
            wa[8]+=A*q2.x; wa[9]+=A*q2.y; wa[10]+=A*q2.z; wa[11]+=A*q2.w;
            wa[12]+=A*q3.x; wa[13]+=A*q3.y; wa[14]+=A*q3.z; wa[15]+=A*q3.w;
            wb[0]+=Bv*q0.x; wb[1]+=Bv*q0.y; wb[2]+=Bv*q0.z; wb[3]+=Bv*q0.w;
            wb[4]+=Bv*q1.x; wb[5]+=Bv*q1.y; wb[6]+=Bv*q1.z; wb[7]+=Bv*q1.w;
            wb[8]+=Bv*q2.x; wb[9]+=Bv*q2.y; wb[10]+=Bv*q2.z; wb[11]+=Bv*q2.w;
            wb[12]+=Bv*q3.x; wb[13]+=Bv*q3.y; wb[14]+=Bv*q3.z; wb[15]+=Bv*q3.w;
        }
#pragma unroll
        for (int t = 0; t < 16; t++) { osA[t] += cfa * wa[t]; osB[t] += cfb * wb[t]; }
    }
}

// vector fold for one half from staged slab (C at [0,4096), D at [4096,6144))
__device__ __forceinline__ void fold_vector_staged(
    const EdgeCtx& c, const float* ha, const float* hb,
    float* ovA, float* ovB)
{
    int lane = c.lane;
    float ra0 = c.shR[lane],      ra1 = c.shR[EPB + lane],      ra2 = c.shR[2 * EPB + lane];
    float rb0 = c.shR[lane + 32], rb1 = c.shR[EPB + lane + 32], rb2 = c.shR[2 * EPB + lane + 32];

#pragma unroll
    for (int t = 0; t < 12; t++) { ovA[t] = 0.0f; ovB[t] = 0.0f; }

    // Block C: slab float4 idx = k*16 + u
#pragma unroll 1
    for (int u = 0; u < 16; u++) {
        float wa[4], wb[4];
#pragma unroll
        for (int t = 0; t < 4; t++) { wa[t] = 0.0f; wb[t] = 0.0f; }
#pragma unroll
        for (int j = 0; j < KC; j++) {
            float4 q = reinterpret_cast<const float4*>(c.shS)[(c.warp * KC + j) * 16 + u];
            float A = ha[j], Bv = hb[j];
            wa[0]+=A*q.x; wa[1]+=A*q.y; wa[2]+=A*q.z; wa[3]+=A*q.w;
            wb[0]+=Bv*q.x; wb[1]+=Bv*q.y; wb[2]+=Bv*q.z; wb[3]+=Bv*q.w;
        }
        float cfa = C24S3 * c.shN[u * EPB + lane];
        float cfb = C24S3 * c.shN[u * EPB + lane + 32];
#pragma unroll
        for (int t = 0; t < 4; t++) {
            float sa = cfa * wa[t], sb = cfb * wb[t];
            ovA[t*3+0] += sa * ra0; ovA[t*3+1] += sa * ra1; ovA[t*3+2] += sa * ra2;
            ovB[t*3+0] += sb * rb0; ovB[t*3+1] += sb * rb1; ovB[t*3+2] += sb * rb2;
        }
    }

    // Block D: slab float4 idx = 1024 + k*8 + u
#pragma unroll 1
    for (int u = 0; u < 8; u++) {
        float wa[4], wb[4];
#pragma unroll
        for (int t = 0; t < 4; t++) { wa[t] = 0.0f; wb[t] = 0.0f; }
#pragma unroll
        for (int j = 0; j < KC; j++) {
            float4 q = reinterpret_cast<const float4*>(c.shS)[1024 + (c.warp * KC + j) * 8 + u];
            float A = ha[j], Bv = hb[j];
            wa[0]+=A*q.x; wa[1]+=A*q.y; wa[2]+=A*q.z; wa[3]+=A*q.w;
            wb[0]+=Bv*q.x; wb[1]+=Bv*q.y; wb[2]+=Bv*q.z; wb[3]+=Bv*q.w;
        }
        float ca0 = C24 * c.shN[(16 + u * 3) * EPB + lane];
        float ca1 = C24 * c.shN[(17 + u * 3) * EPB + lane];
        float ca2 = C24 * c.shN[(18 + u * 3) * EPB + lane];
        float cb0 = C24 * c.shN[(16 + u * 3) * EPB + lane + 32];
        float cb1 = C24 * c.shN[(17 + u * 3) * EPB + lane + 32];
        float cb2 = C24 * c.shN[(18 + u * 3) * EPB + lane + 32];
#pragma unroll
        for (int t = 0; t < 4; t++) {
            ovA[t*3+0] += ca0 * wa[t]; ovA[t*3+1] += ca1 * wa[t]; ovA[t*3+2] += ca2 * wa[t];
            ovB[t*3+0] += cb0 * wb[t]; ovB[t*3+1] += cb1 * wb[t]; ovB[t*3+2] += cb2 * wb[t];
        }
    }
}

// stage one scalar slab round (4 u-columns, all 64 k) coalesced
__device__ __forceinline__ void stage_scalar(
    float* shS, const float* __restrict__ W1, int colbase, int tid)
{
    for (int i4 = tid; i4 < 1024; i4 += TBE) {
        int tq = (i4 & 3) * 4, uu = (i4 >> 2) & 3, k = i4 >> 4;
        float4 v = __ldg(reinterpret_cast<const float4*>(W1 + k * 576 + colbase + uu * 16 + tq));
        reinterpret_cast<float4*>(shS)[i4] = v;
    }
}

// stage vector slab for one half (C: 16 u, D: 8 u)
__device__ __forceinline__ void stage_vector(
    float* shS, const float* __restrict__ W1, int half, int tid)
{
    for (int i4 = tid; i4 < 1024; i4 += TBE) {           // C
        int k = i4 >> 4, u = i4 & 15;
        float4 v = __ldg(reinterpret_cast<const float4*>(W1 + k * 576 + 384 + u * 8 + half * 4));
        reinterpret_cast<float4*>(shS)[i4] = v;
    }
    for (int i4 = tid; i4 < 512; i4 += TBE) {            // D
        int k = i4 >> 3, u = i4 & 7;
        float4 v = __ldg(reinterpret_cast<const float4*>(W1 + k * 576 + 512 + u * 8 + half * 4));
        reinterpret_cast<float4*>(shS)[1024 + i4] = v;
    }
}

// ---------------------------------------------------------------------------
// message kernel: 64 edges / 256 threads, smem-staged weights
// ---------------------------------------------------------------------------
__global__ void __launch_bounds__(TBE, 2) k_msg(
    const float* __restrict__ pos,
    const int* __restrict__ srcI, const int* __restrict__ dstI,
    const float* __restrict__ eattr, int E, int B,
    const float* __restrict__ W0, const float* __restrict__ W1)
{
    __shared__ float shN[NF * EPB];          // 10 KB
    __shared__ float shS[SHS_F];             // 36 KB union slab/slice
    __shared__ float shR[3 * EPB];
    __shared__ int   shSi[EPB];
    __shared__ int   shDi[EPB];

    int tid  = threadIdx.x;
    int lane = tid & 31;
    int warp = tid >> 5;
    int e0 = blockIdx.x * EPB;

    if (tid < EPB) {
        int e = min(e0 + tid, E - 1);
        int si = srcI[e], di = dstI[e];
        shSi[tid] = si; shDi[tid] = di;
        float vx = pos[di * 3 + 0] - pos[si * 3 + 0];
        float vy = pos[di * 3 + 1] - pos[si * 3 + 1];
        float vz = pos[di * 3 + 2] - pos[si * 3 + 2];
        float rn = rsqrtf(vx * vx + vy * vy + vz * vz);
        shR[tid]           = vx * rn;
        shR[EPB + tid]     = vy * rn;
        shR[2 * EPB + tid] = vz * rn;
    }
    __syncthreads();

    for (int i = tid; i < NF * EPB; i += TBE) {
        int e = i & (EPB - 1), f = i >> 6;
        shN[f * EPB + e] = g_node[shSi[e] * NF + f];
    }

    float ha[KC], hb[KC];
    {
        float inv = rsqrtf((float)B);
        int kb = warp * KC;
        int ea = min(e0 + lane, E - 1);
        int eb = min(e0 + lane + 32, E - 1);
        float aa[8], ab[8];
#pragma unroll
        for (int b = 0; b < 8; b++) {
            aa[b] = (b < B) ? eattr[ea * B + b] : 0.0f;
            ab[b] = (b < B) ? eattr[eb * B + b] : 0.0f;
        }
#pragma unroll
        for (int j = 0; j < KC; j++) {
            float sa = 0.0f, sb = 0.0f;
#pragma unroll
            for (int b = 0; b < 8; b++)
                if (b < B) {
                    float w = W0[b * 64 + kb + j];
                    sa += aa[b] * w; sb += ab[b] * w;
                }
            ha[j] = siluN(sa * inv) * 0.125f;
            hb[j] = siluN(sb * inv) * 0.125f;
        }
    }

    EdgeCtx ctx{shN, shR, shS, lane, warp, tid};

    // ---- scalar phase: 6 slab rounds (A u0=0,4,8,12; B u0=0,4) ----
    float osA[16], osB[16];
#pragma unroll
    for (int t = 0; t < 16; t++) { osA[t] = 0.0f; osB[t] = 0.0f; }
#pragma unroll 1
    for (int round = 0; round < 6; round++) {
        int isB = (round >= 4);
        int u0 = isB ? (round - 4) * 4 : round * 4;
        int colbase = isB ? 256 + u0 * 16 : u0 * 16;
        __syncthreads();
        stage_scalar(shS, W1, colbase, tid);
        __syncthreads();
        fold_scalar_round(ctx, ha, hb, u0, isB, osA, osB);
    }
    __syncthreads();
#pragma unroll
    for (int t = 0; t < 16; t++) {
        shS[warp * 16 * EPB + t * EPB + lane]      = osA[t];
        shS[warp * 16 * EPB + t * EPB + lane + 32] = osB[t];
    }
    __syncthreads();
    for (int i = tid; i < 16 * EPB; i += TBE) {
        float s = 0.0f;
#pragma unroll
        for (int w = 0; w < NW; w++) s += shS[w * 16 * EPB + i];
        int e = i & (EPB - 1), f = i >> 6;
        if (e0 + e < E) atomicAdd(&g_msgs[shDi[e] * NF + f], s);
    }

    // ---- vector phases (2 halves; slab [0,6144), slices [6144,9216)) ----
#pragma unroll 1
    for (int half = 0; half < 2; half++) {
        __syncthreads();
        stage_vector(shS, W1, half, tid);
        __syncthreads();
        float ovA[12], ovB[12];
        fold_vector_staged(ctx, ha, hb, ovA, ovB);
#pragma unroll 1
        for (int cch = 0; cch < 2; cch++) {
            __syncthreads();
#pragma unroll
            for (int t = 0; t < 6; t++) {
                shS[6144 + warp * 6 * EPB + t * EPB + lane]      = ovA[cch * 6 + t];
                shS[6144 + warp * 6 * EPB + t * EPB + lane + 32] = ovB[cch * 6 + t];
            }
            __syncthreads();
            for (int i = tid; i < 6 * EPB; i += TBE) {
                float s = 0.0f;
#pragma unroll
                for (int w = 0; w < NW; w++) s += shS[6144 + w * 6 * EPB + i];
                int e = i & (EPB - 1), f = i >> 6;
                if (e0 + e < E)
                    atomicAdd(&g_msgs[shDi[e] * NF + 16 + half * 12 + cch * 6 + f], s);
            }
        }
    }
}

// ---------------------------------------------------------------------------
// ligand embedding (same staging); also zeroes d_out rows for k_rec
// ---------------------------------------------------------------------------
__global__ void __launch_bounds__(TBE, 2) k_lig(
    const float* __restrict__ pos,
    const int* __restrict__ recI, const int* __restrict__ ligI, int EI,
    const float* __restrict__ W0, const float* __restrict__ W1,
    float* __restrict__ out)
{
    __shared__ float shN[NF * EPB];
    __shared__ float shS[SHS_F];
    __shared__ float shR[3 * EPB];
    __shared__ float shD[EPB];
    __shared__ int   shLi[EPB];

    int tid  = threadIdx.x;
    int lane = tid & 31;
    int warp = tid >> 5;
    int e0 = blockIdx.x * EPB;

    for (int i = tid; i < 8 * EPB; i += TBE) {
        int e = i >> 3;
        if (e0 + e < EI) out[(e0 + e) * 8 + (i & 7)] = 0.0f;
    }

    if (tid < EPB) {
        int e = min(e0 + tid, EI - 1);
        int ri = recI[e], li = ligI[e];
        shLi[tid] = li;
        float vx = pos[li * 3 + 0] - pos[ri * 3 + 0];
        float vy = pos[li * 3 + 1] - pos[ri * 3 + 1];
        float vz = pos[li * 3 + 2] - pos[ri * 3 + 2];
        float d2 = vx * vx + vy * vy + vz * vz;
        float invd = rsqrtf(d2);
        shR[tid]           = vx * invd;
        shR[EPB + tid]     = vy * invd;
        shR[2 * EPB + tid] = vz * invd;
        shD[tid]           = d2 * invd;
    }
    __syncthreads();

    for (int i = tid; i < NF * EPB; i += TBE) {
        int e = i & (EPB - 1), f = i >> 6;
        shN[f * EPB + e] = g_node[shLi[e] * NF + f];
    }

    float ha[KC], hb[KC];
    {
        int kb = warp * KC;
        float aa[20], ab[20];
        demb_compute(shD[lane],      aa);
        demb_compute(shD[lane + 32], ab);
#pragma unroll
        for (int j = 0; j < KC; j++) {
            float sa = 0.0f, sb = 0.0f;
#pragma unroll
            for (int i = 0; i < 20; i++) {
                float w = W0[i * 64 + kb + j];
                sa += aa[i] * w; sb += ab[i] * w;
            }
            ha[j] = siluN(sa) * 0.125f;
            hb[j] = siluN(sb) * 0.125f;
        }
    }

    EdgeCtx ctx{shN, shR, shS, lane, warp, tid};

    float osA[16], osB[16];
#pragma unroll
    for (int t = 0; t < 16; t++) { osA[t] = 0.0f; osB[t] = 0.0f; }
#pragma unroll 1
    for (int round = 0; round < 6; round++) {
        int isB = (round >= 4);
        int u0 = isB ? (round - 4) * 4 : round * 4;
        int colbase = isB ? 256 + u0 * 16 : u0 * 16;
        __syncthreads();
        stage_scalar(shS, W1, colbase, tid);
        __syncthreads();
        fold_scalar_round(ctx, ha, hb, u0, isB, osA, osB);
    }
    __syncthreads();
#pragma unroll
    for (int t = 0; t < 16; t++) {
        shS[warp * 16 * EPB + t * EPB + lane]      = osA[t];
        shS[warp * 16 * EPB + t * EPB + lane + 32] = osB[t];
    }
    __syncthreads();
    for (int i = tid; i < 16 * EPB; i += TBE) {
        float s = 0.0f;
#pragma unroll
        for (int w = 0; w < NW; w++) s += shS[w * 16 * EPB + i];
        int e = i & (EPB - 1), f = i >> 6;
        if (e0 + e < EI) g_lig[(e0 + e) * NF + f] = s;
    }

#pragma unroll 1
    for (int half = 0; half < 2; half++) {
        __syncthreads();
        stage_vector(shS, W1, half, tid);
        __syncthreads();
        float ovA[12], ovB[12];
        fold_vector_staged(ctx, ha, hb, ovA, ovB);
#pragma unroll 1
        for (int cch = 0; cch < 2; cch++) {
            __syncthreads();
#pragma unroll
            for (int t = 0; t < 6; t++) {
                shS[6144 + warp * 6 * EPB + t * EPB + lane]      = ovA[cch * 6 + t];
                shS[6144 + warp * 6 * EPB + t * EPB + lane + 32] = ovB[cch * 6 + t];
            }
            __syncthreads();
            for (int i = tid; i < 6 * EPB; i += TBE) {
                float s = 0.0f;
#pragma unroll
                for (int w = 0; w < NW; w++) s += shS[6144 + w * 6 * EPB + i];
                int e = i & (EPB - 1), f = i >> 6;
                if (e0 + e < EI)
                    g_lig[(e0 + e) * NF + 16 + half * 12 + cch * 6 + f] = s;
            }
        }
    }
}

// ---------------------------------------------------------------------------
// receptor TP readout (R13): 128 edges/block, 4 slots/lane, gridDim.y=2
// ---------------------------------------------------------------------------
__global__ void __launch_bounds__(TBE, 2) k_rec(
    const float* __restrict__ pos,
    const int* __restrict__ recI, const int* __restrict__ ligI, int EI,
    const float* __restrict__ W0, const float* __restrict__ W1,
    float* __restrict__ out)
{
    __shared__ float shL [NF * EPR];
    __shared__ float shRn[NF * EPR];
    __shared__ float shD [EPR];
    __shared__ int   shRi[EPR];

    int tid  = threadIdx.x;
    int lane = tid & 31;
    int warp = tid >> 5;
    int e0 = blockIdx.x * EPR;
    int kb = warp * KCR + blockIdx.y * 32;

    if (tid < EPR) {
        int e = min(e0 + tid, EI - 1);
        int ri = recI[e], li = ligI[e];
        shRi[tid] = ri;
        float vx = pos[li * 3 + 0] - pos[ri * 3 + 0];
        float vy = pos[li * 3 + 1] - pos[ri * 3 + 1];
        float vz = pos[li * 3 + 2] - pos[ri * 3 + 2];
        float d2 = vx * vx + vy * vy + vz * vz;
        shD[tid] = d2 * rsqrtf(d2);
    }
    __syncthreads();

    for (int i = tid; i < NF * EPR; i += TBE) {
        int e = i & (EPR - 1), f = i >> 7;
        int ec = min(e0 + e, EI - 1);
        shL [f * EPR + e] = g_lig[ec * NF + f];
        shRn[f * EPR + e] = g_node[shRi[e] * NF + f];
    }

    float h[4][KCR];
    {
#pragma unroll 1
        for (int s = 0; s < 4; s++) {
            float aa[20];
            demb_compute(shD[lane + s * 32], aa);
#pragma unroll
            for (int j = 0; j < KCR; j++) {
                float sm = 0.0f;
#pragma unroll
                for (int i = 0; i < 20; i++) sm += aa[i] * W0[i * 64 + kb + j];
                h[s][j] = siluN(sm) * 0.125f;
            }
        }
    }
    __syncthreads();

    float acc[4][8];
#pragma unroll
    for (int s = 0; s < 4; s++)
#pragma unroll
        for (int t = 0; t < 8; t++) acc[s][t] = 0.0f;
    const float* Wk = W1 + kb * 2560;

#pragma unroll 1
    for (int u = 0; u < 16; u++) {
        float lu[4];
#pragma unroll
        for (int s = 0; s < 4; s++) lu[s] = shL[u * EPR + lane + s * 32];
#pragma unroll 1
        for (int v = 0; v < 16; v++) {
            float cf[4];
#pragma unroll
            for (int s = 0; s < 4; s++) cf[s] = lu[s] * shRn[v * EPR + lane + s * 32];
            const float* base = Wk + (u * 16 + v) * 8;
#pragma unroll
            for (int j = 0; j < KCR; j++) {
                float p[4];
#pragma unroll
                for (int s = 0; s < 4; s++) p[s] = cf[s] * h[s][j];
                const float4* bp = reinterpret_cast<const float4*>(base + j * 2560);
                float4 q0 = __ldg(bp), q1 = __ldg(bp + 1);
#pragma unroll
                for (int s = 0; s < 4; s++) {
                    acc[s][0] += p[s] * q0.x; acc[s][1] += p[s] * q0.y;
                    acc[s][2] += p[s] * q0.z; acc[s][3] += p[s] * q0.w;
                    acc[s][4] += p[s] * q1.x; acc[s][5] += p[s] * q1.y;
                    acc[s][6] += p[s] * q1.z; acc[s][7] += p[s] * q1.w;
                }
            }
        }
    }

#pragma unroll 1
    for (int u = 0; u < 8; u++) {
        float la0[4], la1[4], la2[4];
#pragma unroll
        for (int s = 0; s < 4; s++) {
            int idx = lane + s * 32;
            la0[s] = shL[(16 + u * 3) * EPR + idx];
            la1[s] = shL[(17 + u * 3) * EPR + idx];
            la2[s] = shL[(18 + u * 3) * EPR + idx];
        }
#pragma unroll 1
        for (int v = 0; v < 8; v++) {
            float cf[4];
#pragma unroll
            for (int s = 0; s < 4; s++) {
                int idx = lane + s * 32;
                cf[s] = (la0[s] * shRn[(16 + v * 3) * EPR + idx] +
                         la1[s] * shRn[(17 + v * 3) * EPR + idx] +
                         la2[s] * shRn[(18 + v * 3) * EPR + idx]) * INVS3;
            }
            const float* base = Wk + 2048 + (u * 8 + v) * 8;
#pragma unroll
            for (int j = 0; j < KCR; j++) {
                float p[4];
#pragma unroll
                for (int s = 0; s < 4; s++) p[s] = cf[s] * h[s][j];
                const float4* bp = reinterpret_cast<const float4*>(base + j * 2560);
                float4 q0 = __ldg(bp), q1 = __ldg(bp + 1);
#pragma unroll
                for (int s = 0; s < 4; s++) {
                    acc[s][0] += p[s] * q0.x; acc[s][1] += p[s] * q0.y;
                    acc[s][2] += p[s] * q0.z; acc[s][3] += p[s] * q0.w;
                    acc[s][4] += p[s] * q1.x; acc[s][5] += p[s] * q1.y;
                    acc[s][6] += p[s] * q1.z; acc[s][7] += p[s] * q1.w;
                }
            }
        }
    }

#pragma unroll
    for (int s = 0; s < 4; s++) {
        int e = e0 + lane + s * 32;
        if (e < EI) {
#pragma unroll
            for (int t = 0; t < 8; t++)
                atomicAdd(&out[e * 8 + t], PWREC * acc[s][t]);
        }
    }
}

// ---------------------------------------------------------------------------
// host launcher (graph-capturable: kernel launches only)
// ---------------------------------------------------------------------------
extern "C" void kernel_launch(void* const* d_in, const int* in_sizes, int n_in,
                              void* d_out, int out_size) {
    (void)n_in; (void)out_size;
    const float* x       = (const float*)d_in[0];
    const float* pos     = (const float*)d_in[1];
    const int*   eidx    = (const int*)  d_in[2];
    const float* eattr   = (const float*)d_in[3];
    const int*   iidx    = (const int*)  d_in[4];
    const float* emb_w0  = (const float*)d_in[5];
    const float* emb_w1  = (const float*)d_in[6];
    const float* imp0    = (const float*)d_in[7];
    const float* msg0_w0 = (const float*)d_in[8];
    const float* msg0_w1 = (const float*)d_in[9];
    const float* upd0_w0 = (const float*)d_in[10];
    const float* upd0_w1 = (const float*)d_in[11];
    const float* imp1    = (const float*)d_in[12];
    const float* msg1_w0 = (const float*)d_in[13];
    const float* msg1_w1 = (const float*)d_in[14];
    const float* upd1_w0 = (const float*)d_in[15];
    const float* upd1_w1 = (const float*)d_in[16];
    const float* lig_w0  = (const float*)d_in[17];
    const float* lig_w1  = (const float*)d_in[18];
    const float* rec_w0  = (const float*)d_in[19];
    const float* rec_w1  = (const float*)d_in[20];

    int N  = in_sizes[1] / 3;
    int A  = in_sizes[0] / N;
    int E  = in_sizes[2] / 2;
    int B  = in_sizes[3] / E;
    int EI = in_sizes[4] / 2;
    const int* src  = eidx;
    const int* dst  = eidx + E;
    const int* recI = iidx;
    const int* ligI = iidx + EI;
    float degf = (float)E / (float)N;

    int gn = (N + 63) / 64;
    int ge = (E + EPB - 1) / EPB;
    int gi = (EI + EPB - 1) / EPB;
    dim3 gr((EI + EPR - 1) / EPR, 2);

    k_embed<<<gn, 64>>>(x, N, A, emb_w0, emb_w1);       // also zeroes g_msgs

    k_msg<<<ge, TBE>>>(pos, src, dst, eattr, E, B, msg0_w0, msg0_w1);
    k_update<<<gn, 64>>>(N, imp0, degf, upd0_w0, upd0_w1, 1.0f);   // re-zeroes g_msgs

    k_msg<<<ge, TBE>>>(pos, src, dst, eattr, E, B, msg1_w0, msg1_w1);
    k_update<<<gn, 64>>>(N, imp1, degf, upd1_w0, upd1_w1, 0.5f);

    k_lig<<<gi, TBE>>>(pos, recI, ligI, EI, lig_w0, lig_w1, (float*)d_out);  // zeroes d_out
    k_rec<<<gr, TBE>>>(pos, recI, ligI, EI, rec_w0, rec_w1, (float*)d_out);
}

// round 16
// speedup vs baseline: 1.4621x; 1.0776x over previous
#include <cuda_runtime.h>
#include <math.h>

// ---------------------------------------------------------------------------
// InteractionPredictor: e3nn-style equivariant GNN, fully fused fp32.
// R15 = R14 with the scalar weight-staging merged from 6 rounds of 4
// u-columns to 3 rounds of 8 (slab 32 KB in the 36 KB union): halves the
// stage->sync->fold serialization in the dominant phase and cuts barriers.
// All else identical to R14 (best known): k_msg/k_lig smem-staged weights,
// 64 edges/256 thr, 8 warps x KC=8, 2 edge-slots; k_rec 128 edges, 4 slots,
// gridDim.y=2; k_embed/k_update float4 + 64-thread blocks.
// ---------------------------------------------------------------------------

#define TBE    256         /* threads per edge block      */
#define EPB    64          /* edges per block (msg/lig)   */
#define EPR    128         /* edges per block (rec)       */
#define KC     8           /* k-chunk per warp (msg/lig)  */
#define KCR    4           /* k-chunk per warp (rec)      */
#define NW     8           /* warps per block             */
#define NF     40
#define SHS_F  9216        /* union buffer floats (36 KB) */

__device__ float g_node[16384 * NF];
__device__ float g_msgs[16384 * NF];
__device__ float g_lig [65536 * NF];

#define C24    0.20412414523193154f   /* sqrt(1/24)  */
#define C24S3  0.35355339059327373f   /* sqrt(1/8)   */
#define INVS3  0.57735026918962576f   /* 1/sqrt(3)   */
#define PWREC  0.05590169943749474f   /* 1/sqrt(320) */
#define DEMBC  8.4335731f             /* 1.14136*e^2 */
#define INV32  0.17677669529663687f   /* 1/sqrt(32)  */

__device__ __forceinline__ float siluN(float x) {
    return x * (1.0f / (1.0f + __expf(-x))) * 1.6789717f;
}

// ---------------------------------------------------------------------------
// node embedding (float4 weight loads); also zeroes g_msgs rows
// ---------------------------------------------------------------------------
__global__ void __launch_bounds__(64) k_embed(
    const float* __restrict__ x, int N, int A,
    const float* __restrict__ W0, const float* __restrict__ W1) {
    int n = blockIdx.x * blockDim.x + threadIdx.x;
    if (n >= N) return;
    float inv = rsqrtf((float)A);
    float a[16];
#pragma unroll
    for (int b = 0; b < 16; b++) a[b] = (b < A) ? x[n * A + b] : 0.0f;
    float h[64];
#pragma unroll 4
    for (int kq = 0; kq < 16; kq++) {
        float s0 = 0.0f, s1 = 0.0f, s2 = 0.0f, s3 = 0.0f;
#pragma unroll
        for (int b = 0; b < 16; b++)
            if (b < A) {
                float4 w = __ldg(reinterpret_cast<const float4*>(W0 + b * 64 + kq * 4));
                s0 += a[b] * w.x; s1 += a[b] * w.y; s2 += a[b] * w.z; s3 += a[b] * w.w;
            }
        h[kq * 4 + 0] = siluN(s0 * inv) * 0.125f;
        h[kq * 4 + 1] = siluN(s1 * inv) * 0.125f;
        h[kq * 4 + 2] = siluN(s2 * inv) * 0.125f;
        h[kq * 4 + 3] = siluN(s3 * inv) * 0.125f;
    }
    float* nr = g_node + n * NF;
#pragma unroll
    for (int wq = 0; wq < 4; wq++) {
        float s0 = 0.0f, s1 = 0.0f, s2 = 0.0f, s3 = 0.0f;
#pragma unroll 8
        for (int k = 0; k < 64; k++) {
            float4 w = __ldg(reinterpret_cast<const float4*>(W1 + k * 16 + wq * 4));
            float hk = h[k];
            s0 += hk * w.x; s1 += hk * w.y; s2 += hk * w.z; s3 += hk * w.w;
        }
        nr[wq * 4 + 0] = s0; nr[wq * 4 + 1] = s1;
        nr[wq * 4 + 2] = s2; nr[wq * 4 + 3] = s3;
    }
#pragma unroll
    for (int t = 0; t < 24; t++) nr[16 + t] = 0.0f;
    float* mr = g_msgs + n * NF;
#pragma unroll
    for (int t = 0; t < NF; t++) mr[t] = 0.0f;
}

// ---------------------------------------------------------------------------
// node update (float4 weight loads); re-zeroes msg row after consuming
// ---------------------------------------------------------------------------
__global__ void __launch_bounds__(64) k_update(
    int N, const float* __restrict__ imp, float degf,
    const float* __restrict__ W0, const float* __restrict__ W1, float gmul) {
    int n = blockIdx.x * blockDim.x + threadIdx.x;
    if (n >= N) return;
    float scale = imp[0] * rsqrtf(degf);
    float* nr = g_node + n * NF;
    float* mr = g_msgs + n * NF;
    float a[32];
#pragma unroll
    for (int t = 0; t < 16; t++) a[t] = mr[t] * scale;
#pragma unroll
    for (int t = 0; t < 16; t++) a[16 + t] = nr[t];
    float ge[24];
#pragma unroll
    for (int t = 0; t < 24; t++) ge[t] = (mr[16 + t] * scale + nr[16 + t]) * gmul;
#pragma unroll
    for (int t = 0; t < NF; t++) mr[t] = 0.0f;
    float h[64];
#pragma unroll 2
    for (int kq = 0; kq < 16; kq++) {
        float s0 = 0.0f, s1 = 0.0f, s2 = 0.0f, s3 = 0.0f;
#pragma unroll
        for (int b = 0; b < 32; b++) {
            float4 w = __ldg(reinterpret_cast<const float4*>(W0 + b * 64 + kq * 4));
            float ab = a[b];
            s0 += ab * w.x; s1 += ab * w.y; s2 += ab * w.z; s3 += ab * w.w;
        }
        h[kq * 4 + 0] = siluN(s0 * INV32) * 0.125f;
        h[kq * 4 + 1] = siluN(s1 * INV32) * 0.125f;
        h[kq * 4 + 2] = siluN(s2 * INV32) * 0.125f;
        h[kq * 4 + 3] = siluN(s3 * INV32) * 0.125f;
    }
    float sc[16];
#pragma unroll
    for (int wq = 0; wq < 4; wq++) {
        float s0 = 0.0f, s1 = 0.0f, s2 = 0.0f, s3 = 0.0f;
#pragma unroll 8
        for (int k = 0; k < 64; k++) {
            float4 w = __ldg(reinterpret_cast<const float4*>(W1 + k * 16 + wq * 4));
            float hk = h[k];
            s0 += hk * w.x; s1 += hk * w.y; s2 += hk * w.z; s3 += hk * w.w;
        }
        sc[wq * 4 + 0] = s0; sc[wq * 4 + 1] = s1;
        sc[wq * 4 + 2] = s2; sc[wq * 4 + 3] = s3;
    }
#pragma unroll
    for (int w = 0; w < 16; w++) nr[w] = sc[w];
#pragma unroll
    for (int t = 0; t < 24; t++) nr[16 + t] = ge[t];
}

// ---------------------------------------------------------------------------
__device__ __forceinline__ void demb_compute(float d, float* a) {
    float tt = d * 4.2f;
#pragma unroll
    for (int i = 0; i < 20; i++) {
        float diff = tt - (float)(i + 1);
        float p = diff + 1.0f, q = 1.0f - diff;
        float s1 = (p > 0.0f) ? __expf(-1.0f / p) : 0.0f;
        float s2 = (q > 0.0f) ? __expf(-1.0f / q) : 0.0f;
        a[i] = DEMBC * s1 * s2;
    }
}

// ---------------------------------------------------------------------------
// Shared edge-kernel body: smem-staged weights. Used by k_msg and k_lig.
// shS layout (floats, total SHS_F = 9216 = 36 KB):
//   scalar phase: slab rounds (8 u-cols) use [0, 8192); slices use [0, 8192)
//   vector phase: slab (C 4096 + D 2048) at [0, 6144); slices [6144, 9216)
// ---------------------------------------------------------------------------
struct EdgeCtx {
    const float* shN;   // node feats [40][EPB]
    const float* shR;   // unit vec [3][EPB]
    float* shS;
    int lane, warp, tid;
};

// fold one scalar round (8 u's of A or B) from the staged slab
// slab float4 layout: idx = (k*8 + uu)*4 + tq  (k = warp*KC + j)
__device__ __forceinline__ void fold_scalar_round8(
    const EdgeCtx& c, const float* ha, const float* hb,
    int u0, int isB, float* osA, float* osB)
{
    int lane = c.lane;
#pragma unroll 1
    for (int uu = 0; uu < 8; uu++) {
        int u = u0 + uu;
        float cfa, cfb;
        if (!isB) {
            cfa = C24 * c.shN[u * EPB + lane];
            cfb = C24 * c.shN[u * EPB + lane + 32];
        } else {
            cfa = C24 * (c.shN[(16 + u * 3) * EPB + lane] * c.shR[lane] +
                         c.shN[(17 + u * 3) * EPB + lane] * c.shR[EPB + lane] +
                         c.shN[(18 + u * 3) * EPB + lane] * c.shR[2 * EPB + lane]);
            cfb = C24 * (c.shN[(16 + u * 3) * EPB + lane + 32] * c.shR[lane + 32] +
                         c.shN[(17 + u * 3) * EPB + lane + 32] * c.shR[EPB + lane + 32] +
                         c.shN[(18 + u * 3) * EPB + lane + 32] * c.shR[2 * EPB + lane + 32]);
        }
        float wa[16], wb[16];
#pragma unroll
        for (int t = 0; t < 16; t++) { wa[t] = 0.0f; wb[t] = 0.0f; }
#pragma unroll
        for (int j = 0; j < KC; j++) {
            const float4* p = reinterpret_cast<const float4*>(
                c.shS + ((c.warp * KC + j) * 8 + uu) * 16);
            float4 q0 = p[0], q1 = p[1], q2 = p[2], q3 = p[3];
            float A = ha[j], Bv = hb[j];
            wa[0]+=A*q0.x; wa[1]+=A*q0.y; wa[2]+=A*q0.z; wa[3]+=A*q0.w;
            wa[4]+=A*q1.x; wa[5]+=A*q1.y; wa[6]+=A*q1.z; wa[7]+=A*q1.w;
            wa[8]+=A*q2.x; wa[9]+=A*q2.y; wa[10]+=A*q2.z; wa[11]+=A*q2.w;
            wa[12]+=A*q3.x; wa[13]+=A*q3.y; wa[14]+=A*q3.z; wa[15]+=A*q3.w;
            wb[0]+=Bv*q0.x; wb[1]+=Bv*q0.y; wb[2]+=Bv*q0.z; wb[3]+=Bv*q0.w;
            wb[4]+=Bv*q1.x; wb[5]+=Bv*q1.y; wb[6]+=Bv*q1.z; wb[7]+=Bv*q1.w;
            wb[8]+=Bv*q2.x; wb[9]+=Bv*q2.y; wb[10]+=Bv*q2.z; wb[11]+=Bv*q2.w;
            wb[12]+=Bv*q3.x; wb[13]+=Bv*q3.y; wb[14]+=Bv*q3.z; wb[15]+=Bv*q3.w;
        }
#pragma unroll
        for (int t = 0; t < 16; t++) { osA[t] += cfa * wa[t]; osB[t] += cfb * wb[t]; }
    }
}

// vector fold for one half from staged slab (C at [0,4096), D at [4096,6144))
__device__ __forceinline__ void fold_vector_staged(
    const EdgeCtx& c, const float* ha, const float* hb,
    float* ovA, float* ovB)
{
    int lane = c.lane;
    float ra0 = c.shR[lane],      ra1 = c.shR[EPB + lane],      ra2 = c.shR[2 * EPB + lane];
    float rb0 = c.shR[lane + 32], rb1 = c.shR[EPB + lane + 32], rb2 = c.shR[2 * EPB + lane + 32];

#pragma unroll
    for (int t = 0; t < 12; t++) { ovA[t] = 0.0f; ovB[t] = 0.0f; }

    // Block C: slab float4 idx = k*16 + u
#pragma unroll 1
    for (int u = 0; u < 16; u++) {
        float wa[4], wb[4];
#pragma unroll
        for (int t = 0; t < 4; t++) { wa[t] = 0.0f; wb[t] = 0.0f; }
#pragma unroll
        for (int j = 0; j < KC; j++) {
            float4 q = reinterpret_cast<const float4*>(c.shS)[(c.warp * KC + j) * 16 + u];
            float A = ha[j], Bv = hb[j];
            wa[0]+=A*q.x; wa[1]+=A*q.y; wa[2]+=A*q.z; wa[3]+=A*q.w;
            wb[0]+=Bv*q.x; wb[1]+=Bv*q.y; wb[2]+=Bv*q.z; wb[3]+=Bv*q.w;
        }
        float cfa = C24S3 * c.shN[u * EPB + lane];
        float cfb = C24S3 * c.shN[u * EPB + lane + 32];
#pragma unroll
        for (int t = 0; t < 4; t++) {
            float sa = cfa * wa[t], sb = cfb * wb[t];
            ovA[t*3+0] += sa * ra0; ovA[t*3+1] += sa * ra1; ovA[t*3+2] += sa * ra2;
            ovB[t*3+0] += sb * rb0; ovB[t*3+1] += sb * rb1; ovB[t*3+2] += sb * rb2;
        }
    }

    // Block D: slab float4 idx = 1024 + k*8 + u
#pragma unroll 1
    for (int u = 0; u < 8; u++) {
        float wa[4], wb[4];
#pragma unroll
        for (int t = 0; t < 4; t++) { wa[t] = 0.0f; wb[t] = 0.0f; }
#pragma unroll
        for (int j = 0; j < KC; j++) {
            float4 q = reinterpret_cast<const float4*>(c.shS)[1024 + (c.warp * KC + j) * 8 + u];
            float A = ha[j], Bv = hb[j];
            wa[0]+=A*q.x; wa[1]+=A*q.y; wa[2]+=A*q.z; wa[3]+=A*q.w;
            wb[0]+=Bv*q.x; wb[1]+=Bv*q.y; wb[2]+=Bv*q.z; wb[3]+=Bv*q.w;
        }
        float ca0 = C24 * c.shN[(16 + u * 3) * EPB + lane];
        float ca1 = C24 * c.shN[(17 + u * 3) * EPB + lane];
        float ca2 = C24 * c.shN[(18 + u * 3) * EPB + lane];
        float cb0 = C24 * c.shN[(16 + u * 3) * EPB + lane + 32];
        float cb1 = C24 * c.shN[(17 + u * 3) * EPB + lane + 32];
        float cb2 = C24 * c.shN[(18 + u * 3) * EPB + lane + 32];
#pragma unroll
        for (int t = 0; t < 4; t++) {
            ovA[t*3+0] += ca0 * wa[t]; ovA[t*3+1] += ca1 * wa[t]; ovA[t*3+2] += ca2 * wa[t];
            ovB[t*3+0] += cb0 * wb[t]; ovB[t*3+1] += cb1 * wb[t]; ovB[t*3+2] += cb2 * wb[t];
        }
    }
}

// stage one scalar slab round (8 u-columns, all 64 k) coalesced
// slab float4 index: (k*8 + uu)*4 + tq
__device__ __forceinline__ void stage_scalar8(
    float* shS, const float* __restrict__ W1, int colbase, int tid)
{
    for (int i4 = tid; i4 < 2048; i4 += TBE) {
        int tq = (i4 & 3) * 4, uu = (i4 >> 2) & 7, k = i4 >> 5;
        float4 v = __ldg(reinterpret_cast<const float4*>(W1 + k * 576 + colbase + uu * 16 + tq));
        reinterpret_cast<float4*>(shS)[i4] = v;
    }
}

// stage vector slab for one half (C: 16 u, D: 8 u)
__device__ __forceinline__ void stage_vector(
    float* shS, const float* __restrict__ W1, int half, int tid)
{
    for (int i4 = tid; i4 < 1024; i4 += TBE) {           // C
        int k = i4 >> 4, u = i4 & 15;
        float4 v = __ldg(reinterpret_cast<const float4*>(W1 + k * 576 + 384 + u * 8 + half * 4));
        reinterpret_cast<float4*>(shS)[i4] = v;
    }
    for (int i4 = tid; i4 < 512; i4 += TBE) {            // D
        int k = i4 >> 3, u = i4 & 7;
        float4 v = __ldg(reinterpret_cast<const float4*>(W1 + k * 576 + 512 + u * 8 + half * 4));
        reinterpret_cast<float4*>(shS)[1024 + i4] = v;
    }
}

// ---------------------------------------------------------------------------
// message kernel: 64 edges / 256 threads, smem-staged weights (3+2 rounds)
// ---------------------------------------------------------------------------
__global__ void __launch_bounds__(TBE, 2) k_msg(
    const float* __restrict__ pos,
    const int* __restrict__ srcI, const int* __restrict__ dstI,
    const float* __restrict__ eattr, int E, int B,
    const float* __restrict__ W0, const float* __restrict__ W1)
{
    __shared__ float shN[NF * EPB];          // 10 KB
    __shared__ float shS[SHS_F];             // 36 KB union slab/slice
    __shared__ float shR[3 * EPB];
    __shared__ int   shSi[EPB];
    __shared__ int   shDi[EPB];

    int tid  = threadIdx.x;
    int lane = tid & 31;
    int warp = tid >> 5;
    int e0 = blockIdx.x * EPB;

    if (tid < EPB) {
        int e = min(e0 + tid, E - 1);
        int si = srcI[e], di = dstI[e];
        shSi[tid] = si; shDi[tid] = di;
        float vx = pos[di * 3 + 0] - pos[si * 3 + 0];
        float vy = pos[di * 3 + 1] - pos[si * 3 + 1];
        float vz = pos[di * 3 + 2] - pos[si * 3 + 2];
        float rn = rsqrtf(vx * vx + vy * vy + vz * vz);
        shR[tid]           = vx * rn;
        shR[EPB + tid]     = vy * rn;
        shR[2 * EPB + tid] = vz * rn;
    }
    __syncthreads();

    for (int i = tid; i < NF * EPB; i += TBE) {
        int e = i & (EPB - 1), f = i >> 6;
        shN[f * EPB + e] = g_node[shSi[e] * NF + f];
    }

    float ha[KC], hb[KC];
    {
        float inv = rsqrtf((float)B);
        int kb = warp * KC;
        int ea = min(e0 + lane, E - 1);
        int eb = min(e0 + lane + 32, E - 1);
        float aa[8], ab[8];
#pragma unroll
        for (int b = 0; b < 8; b++) {
            aa[b] = (b < B) ? eattr[ea * B + b] : 0.0f;
            ab[b] = (b < B) ? eattr[eb * B + b] : 0.0f;
        }
#pragma unroll
        for (int j = 0; j < KC; j++) {
            float sa = 0.0f, sb = 0.0f;
#pragma unroll
            for (int b = 0; b < 8; b++)
                if (b < B) {
                    float w = W0[b * 64 + kb + j];
                    sa += aa[b] * w; sb += ab[b] * w;
                }
            ha[j] = siluN(sa * inv) * 0.125f;
            hb[j] = siluN(sb * inv) * 0.125f;
        }
    }

    EdgeCtx ctx{shN, shR, shS, lane, warp, tid};

    // ---- scalar phase: 3 slab rounds (A u0=0; A u0=8; B u0=0) ----
    float osA[16], osB[16];
#pragma unroll
    for (int t = 0; t < 16; t++) { osA[t] = 0.0f; osB[t] = 0.0f; }
#pragma unroll 1
    for (int round = 0; round < 3; round++) {
        int isB = (round == 2);
        int u0 = (round == 1) ? 8 : 0;
        int colbase = isB ? 256 : u0 * 16;
        __syncthreads();
        stage_scalar8(shS, W1, colbase, tid);
        __syncthreads();
        fold_scalar_round8(ctx, ha, hb, u0, isB, osA, osB);
    }
    __syncthreads();
#pragma unroll
    for (int t = 0; t < 16; t++) {
        shS[warp * 16 * EPB + t * EPB + lane]      = osA[t];
        shS[warp * 16 * EPB + t * EPB + lane + 32] = osB[t];
    }
    __syncthreads();
    for (int i = tid; i < 16 * EPB; i += TBE) {
        float s = 0.0f;
#pragma unroll
        for (int w = 0; w < NW; w++) s += shS[w * 16 * EPB + i];
        int e = i & (EPB - 1), f = i >> 6;
        if (e0 + e < E) atomicAdd(&g_msgs[shDi[e] * NF + f], s);
    }

    // ---- vector phases (2 halves; slab [0,6144), slices [6144,9216)) ----
#pragma unroll 1
    for (int half = 0; half < 2; half++) {
        __syncthreads();
        stage_vector(shS, W1, half, tid);
        __syncthreads();
        float ovA[12], ovB[12];
        fold_vector_staged(ctx, ha, hb, ovA, ovB);
#pragma unroll 1
        for (int cch = 0; cch < 2; cch++) {
            __syncthreads();
#pragma unroll
            for (int t = 0; t < 6; t++) {
                shS[6144 + warp * 6 * EPB + t * EPB + lane]      = ovA[cch * 6 + t];
                shS[6144 + warp * 6 * EPB + t * EPB + lane + 32] = ovB[cch * 6 + t];
            }
            __syncthreads();
            for (int i = tid; i < 6 * EPB; i += TBE) {
                float s = 0.0f;
#pragma unroll
                for (int w = 0; w < NW; w++) s += shS[6144 + w * 6 * EPB + i];
                int e = i & (EPB - 1), f = i >> 6;
                if (e0 + e < E)
                    atomicAdd(&g_msgs[shDi[e] * NF + 16 + half * 12 + cch * 6 + f], s);
            }
        }
    }
}

// ---------------------------------------------------------------------------
// ligand embedding (same staging); also zeroes d_out rows for k_rec
// ---------------------------------------------------------------------------
__global__ void __launch_bounds__(TBE, 2) k_lig(
    const float* __restrict__ pos,
    const int* __restrict__ recI, const int* __restrict__ ligI, int EI,
    const float* __restrict__ W0, const float* __restrict__ W1,
    float* __restrict__ out)
{
    __shared__ float shN[NF * EPB];
    __shared__ float shS[SHS_F];
    __shared__ float shR[3 * EPB];
    __shared__ float shD[EPB];
    __shared__ int   shLi[EPB];

    int tid  = threadIdx.x;
    int lane = tid & 31;
    int warp = tid >> 5;
    int e0 = blockIdx.x * EPB;

    for (int i = tid; i < 8 * EPB; i += TBE) {
        int e = i >> 3;
        if (e0 + e < EI) out[(e0 + e) * 8 + (i & 7)] = 0.0f;
    }

    if (tid < EPB) {
        int e = min(e0 + tid, EI - 1);
        int ri = recI[e], li = ligI[e];
        shLi[tid] = li;
        float vx = pos[li * 3 + 0] - pos[ri * 3 + 0];
        float vy = pos[li * 3 + 1] - pos[ri * 3 + 1];
        float vz = pos[li * 3 + 2] - pos[ri * 3 + 2];
        float d2 = vx * vx + vy * vy + vz * vz;
        float invd = rsqrtf(d2);
        shR[tid]           = vx * invd;
        shR[EPB + tid]     = vy * invd;
        shR[2 * EPB + tid] = vz * invd;
        shD[tid]           = d2 * invd;
    }
    __syncthreads();

    for (int i = tid; i < NF * EPB; i += TBE) {
        int e = i & (EPB - 1), f = i >> 6;
        shN[f * EPB + e] = g_node[shLi[e] * NF + f];
    }

    float ha[KC], hb[KC];
    {
        int kb = warp * KC;
        float aa[20], ab[20];
        demb_compute(shD[lane],      aa);
        demb_compute(shD[lane + 32], ab);
#pragma unroll
        for (int j = 0; j < KC; j++) {
            float sa = 0.0f, sb = 0.0f;
#pragma unroll
            for (int i = 0; i < 20; i++) {
                float w = W0[i * 64 + kb + j];
                sa += aa[i] * w; sb += ab[i] * w;
            }
            ha[j] = siluN(sa) * 0.125f;
            hb[j] = siluN(sb) * 0.125f;
        }
    }

    EdgeCtx ctx{shN, shR, shS, lane, warp, tid};

    float osA[16], osB[16];
#pragma unroll
    for (int t = 0; t < 16; t++) { osA[t] = 0.0f; osB[t] = 0.0f; }
#pragma unroll 1
    for (int round = 0; round < 3; round++) {
        int isB = (round == 2);
        int u0 = (round == 1) ? 8 : 0;
        int colbase = isB ? 256 : u0 * 16;
        __syncthreads();
        stage_scalar8(shS, W1, colbase, tid);
        __syncthreads();
        fold_scalar_round8(ctx, ha, hb, u0, isB, osA, osB);
    }
    __syncthreads();
#pragma unroll
    for (int t = 0; t < 16; t++) {
        shS[warp * 16 * EPB + t * EPB + lane]      = osA[t];
        shS[warp * 16 * EPB + t * EPB + lane + 32] = osB[t];
    }
    __syncthreads();
    for (int i = tid; i < 16 * EPB; i += TBE) {
        float s = 0.0f;
#pragma unroll
        for (int w = 0; w < NW; w++) s += shS[w * 16 * EPB + i];
        int e = i & (EPB - 1), f = i >> 6;
        if (e0 + e < EI) g_lig[(e0 + e) * NF + f] = s;
    }

#pragma unroll 1
    for (int half = 0; half < 2; half++) {
        __syncthreads();
        stage_vector(shS, W1, half, tid);
        __syncthreads();
        float ovA[12], ovB[12];
        fold_vector_staged(ctx, ha, hb, ovA, ovB);
#pragma unroll 1
        for (int cch = 0; cch < 2; cch++) {
            __syncthreads();
#pragma unroll
            for (int t = 0; t < 6; t++) {
                shS[6144 + warp * 6 * EPB + t * EPB + lane]      = ovA[cch * 6 + t];
                shS[6144 + warp * 6 * EPB + t * EPB + lane + 32] = ovB[cch * 6 + t];
            }
            __syncthreads();
            for (int i = tid; i < 6 * EPB; i += TBE) {
                float s = 0.0f;
#pragma unroll
                for (int w = 0; w < NW; w++) s += shS[6144 + w * 6 * EPB + i];
                int e = i & (EPB - 1), f = i >> 6;
                if (e0 + e < EI)
                    g_lig[(e0 + e) * NF + 16 + half * 12 + cch * 6 + f] = s;
            }
        }
    }
}

// ---------------------------------------------------------------------------
// receptor TP readout (R13): 128 edges/block, 4 slots/lane, gridDim.y=2
// ---------------------------------------------------------------------------
__global__ void __launch_bounds__(TBE, 2) k_rec(
    const float* __restrict__ pos,
    const int* __restrict__ recI, const int* __restrict__ ligI, int EI,
    const float* __restrict__ W0, const float* __restrict__ W1,
    float* __restrict__ out)
{
    __shared__ float shL [NF * EPR];
    __shared__ float shRn[NF * EPR];
    __shared__ float shD [EPR];
    __shared__ int   shRi[EPR];

    int tid  = threadIdx.x;
    int lane = tid & 31;
    int warp = tid >> 5;
    int e0 = blockIdx.x * EPR;
    int kb = warp * KCR + blockIdx.y * 32;

    if (tid < EPR) {
        int e = min(e0 + tid, EI - 1);
        int ri = recI[e], li = ligI[e];
        shRi[tid] = ri;
        float vx = pos[li * 3 + 0] - pos[ri * 3 + 0];
        float vy = pos[li * 3 + 1] - pos[ri * 3 + 1];
        float vz = pos[li * 3 + 2] - pos[ri * 3 + 2];
        float d2 = vx * vx + vy * vy + vz * vz;
        shD[tid] = d2 * rsqrtf(d2);
    }
    __syncthreads();

    for (int i = tid; i < NF * EPR; i += TBE) {
        int e = i & (EPR - 1), f = i >> 7;
        int ec = min(e0 + e, EI - 1);
        shL [f * EPR + e] = g_lig[ec * NF + f];
        shRn[f * EPR + e] = g_node[shRi[e] * NF + f];
    }

    float h[4][KCR];
    {
#pragma unroll 1
        for (int s = 0; s < 4; s++) {
            float aa[20];
            demb_compute(shD[lane + s * 32], aa);
#pragma unroll
            for (int j = 0; j < KCR; j++) {
                float sm = 0.0f;
#pragma unroll
                for (int i = 0; i < 20; i++) sm += aa[i] * W0[i * 64 + kb + j];
                h[s][j] = siluN(sm) * 0.125f;
            }
        }
    }
    __syncthreads();

    float acc[4][8];
#pragma unroll
    for (int s = 0; s < 4; s++)
#pragma unroll
        for (int t = 0; t < 8; t++) acc[s][t] = 0.0f;
    const float* Wk = W1 + kb * 2560;

#pragma unroll 1
    for (int u = 0; u < 16; u++) {
        float lu[4];
#pragma unroll
        for (int s = 0; s < 4; s++) lu[s] = shL[u * EPR + lane + s * 32];
#pragma unroll 1
        for (int v = 0; v < 16; v++) {
            float cf[4];
#pragma unroll
            for (int s = 0; s < 4; s++) cf[s] = lu[s] * shRn[v * EPR + lane + s * 32];
            const float* base = Wk + (u * 16 + v) * 8;
#pragma unroll
            for (int j = 0; j < KCR; j++) {
                float p[4];
#pragma unroll
                for (int s = 0; s < 4; s++) p[s] = cf[s] * h[s][j];
                const float4* bp = reinterpret_cast<const float4*>(base + j * 2560);
                float4 q0 = __ldg(bp), q1 = __ldg(bp + 1);
#pragma unroll
                for (int s = 0; s < 4; s++) {
                    acc[s][0] += p[s] * q0.x; acc[s][1] += p[s] * q0.y;
                    acc[s][2] += p[s] * q0.z; acc[s][3] += p[s] * q0.w;
                    acc[s][4] += p[s] * q1.x; acc[s][5] += p[s] * q1.y;
                    acc[s][6] += p[s] * q1.z; acc[s][7] += p[s] * q1.w;
                }
            }
        }
    }

#pragma unroll 1
    for (int u = 0; u < 8; u++) {
        float la0[4], la1[4], la2[4];
#pragma unroll
        for (int s = 0; s < 4; s++) {
            int idx = lane + s * 32;
            la0[s] = shL[(16 + u * 3) * EPR + idx];
            la1[s] = shL[(17 + u * 3) * EPR + idx];
            la2[s] = shL[(18 + u * 3) * EPR + idx];
        }
#pragma unroll 1
        for (int v = 0; v < 8; v++) {
            float cf[4];
#pragma unroll
            for (int s = 0; s < 4; s++) {
                int idx = lane + s * 32;
                cf[s] = (la0[s] * shRn[(16 + v * 3) * EPR + idx] +
                         la1[s] * shRn[(17 + v * 3) * EPR + idx] +
                         la2[s] * shRn[(18 + v * 3) * EPR + idx]) * INVS3;
            }
            const float* base = Wk + 2048 + (u * 8 + v) * 8;
#pragma unroll
            for (int j = 0; j < KCR; j++) {
                float p[4];
#pragma unroll
                for (int s = 0; s < 4; s++) p[s] = cf[s] * h[s][j];
                const float4* bp = reinterpret_cast<const float4*>(base + j * 2560);
                float4 q0 = __ldg(bp), q1 = __ldg(bp + 1);
#pragma unroll
                for (int s = 0; s < 4; s++) {
                    acc[s][0] += p[s] * q0.x; acc[s][1] += p[s] * q0.y;
                    acc[s][2] += p[s] * q0.z; acc[s][3] += p[s] * q0.w;
                    acc[s][4] += p[s] * q1.x; acc[s][5] += p[s] * q1.y;
                    acc[s][6] += p[s] * q1.z; acc[s][7] += p[s] * q1.w;
                }
            }
        }
    }

#pragma unroll
    for (int s = 0; s < 4; s++) {
        int e = e0 + lane + s * 32;
        if (e < EI) {
#pragma unroll
            for (int t = 0; t < 8; t++)
                atomicAdd(&out[e * 8 + t], PWREC * acc[s][t]);
        }
    }
}

// ---------------------------------------------------------------------------
// host launcher (graph-capturable: kernel launches only)
// ---------------------------------------------------------------------------
extern "C" void kernel_launch(void* const* d_in, const int* in_sizes, int n_in,
                              void* d_out, int out_size) {
    (void)n_in; (void)out_size;
    const float* x       = (const float*)d_in[0];
    const float* pos     = (const float*)d_in[1];
    const int*   eidx    = (const int*)  d_in[2];
    const float* eattr   = (const float*)d_in[3];
    const int*   iidx    = (const int*)  d_in[4];
    const float* emb_w0  = (const float*)d_in[5];
    const float* emb_w1  = (const float*)d_in[6];
    const float* imp0    = (const float*)d_in[7];
    const float* msg0_w0 = (const float*)d_in[8];
    const float* msg0_w1 = (const float*)d_in[9];
    const float* upd0_w0 = (const float*)d_in[10];
    const float* upd0_w1 = (const float*)d_in[11];
    const float* imp1    = (const float*)d_in[12];
    const float* msg1_w0 = (const float*)d_in[13];
    const float* msg1_w1 = (const float*)d_in[14];
    const float* upd1_w0 = (const float*)d_in[15];
    const float* upd1_w1 = (const float*)d_in[16];
    const float* lig_w0  = (const float*)d_in[17];
    const float* lig_w1  = (const float*)d_in[18];
    const float* rec_w0  = (const float*)d_in[19];
    const float* rec_w1  = (const float*)d_in[20];

    int N  = in_sizes[1] / 3;
    int A  = in_sizes[0] / N;
    int E  = in_sizes[2] / 2;
    int B  = in_sizes[3] / E;
    int EI = in_sizes[4] / 2;
    const int* src  = eidx;
    const int* dst  = eidx + E;
    const int* recI = iidx;
    const int* ligI = iidx + EI;
    float degf = (float)E / (float)N;

    int gn = (N + 63) / 64;
    int ge = (E + EPB - 1) / EPB;
    int gi = (EI + EPB - 1) / EPB;
    dim3 gr((EI + EPR - 1) / EPR, 2);

    k_embed<<<gn, 64>>>(x, N, A, emb_w0, emb_w1);       // also zeroes g_msgs

    k_msg<<<ge, TBE>>>(pos, src, dst, eattr, E, B, msg0_w0, msg0_w1);
    k_update<<<gn, 64>>>(N, imp0, degf, upd0_w0, upd0_w1, 1.0f);   // re-zeroes g_msgs

    k_msg<<<ge, TBE>>>(pos, src, dst, eattr, E, B, msg1_w0, msg1_w1);
    k_update<<<gn, 64>>>(N, imp1, degf, upd1_w0, upd1_w1, 0.5f);

    k_lig<<<gi, TBE>>>(pos, recI, ligI, EI, lig_w0, lig_w1, (float*)d_out);  // zeroes d_out
    k_rec<<<gr, TBE>>>(pos, recI, ligI, EI, rec_w0, rec_w1, (float*)d_out);
}

// round 17
// speedup vs baseline: 1.5478x; 1.0586x over previous
#include <cuda_runtime.h>
#include <math.h>

// ---------------------------------------------------------------------------
// InteractionPredictor: e3nn-style equivariant GNN, fully fused fp32.
// R16 = R15 with the scalar fold converted to the p-scheme (p = cf*h folded
// directly into osA/osB; no wa/wb weight accumulators) which cuts ~32 live
// registers and the per-u epilogue FMAs, enabling __launch_bounds__(256,3)
// on k_msg/k_lig: 3 blocks/SM -> 24 warps (occ 24%->36%) to hide the
// remaining latency stalls. All else identical to R15 (best known).
// ---------------------------------------------------------------------------

#define TBE    256         /* threads per edge block      */
#define EPB    64          /* edges per block (msg/lig)   */
#define EPR    128         /* edges per block (rec)       */
#define KC     8           /* k-chunk per warp (msg/lig)  */
#define KCR    4           /* k-chunk per warp (rec)      */
#define NW     8           /* warps per block             */
#define NF     40
#define SHS_F  9216        /* union buffer floats (36 KB) */

__device__ float g_node[16384 * NF];
__device__ float g_msgs[16384 * NF];
__device__ float g_lig [65536 * NF];

#define C24    0.20412414523193154f   /* sqrt(1/24)  */
#define C24S3  0.35355339059327373f   /* sqrt(1/8)   */
#define INVS3  0.57735026918962576f   /* 1/sqrt(3)   */
#define PWREC  0.05590169943749474f   /* 1/sqrt(320) */
#define DEMBC  8.4335731f             /* 1.14136*e^2 */
#define INV32  0.17677669529663687f   /* 1/sqrt(32)  */

__device__ __forceinline__ float siluN(float x) {
    return x * (1.0f / (1.0f + __expf(-x))) * 1.6789717f;
}

// ---------------------------------------------------------------------------
// node embedding (float4 weight loads); also zeroes g_msgs rows
// ---------------------------------------------------------------------------
__global__ void __launch_bounds__(64) k_embed(
    const float* __restrict__ x, int N, int A,
    const float* __restrict__ W0, const float* __restrict__ W1) {
    int n = blockIdx.x * blockDim.x + threadIdx.x;
    if (n >= N) return;
    float inv = rsqrtf((float)A);
    float a[16];
#pragma unroll
    for (int b = 0; b < 16; b++) a[b] = (b < A) ? x[n * A + b] : 0.0f;
    float h[64];
#pragma unroll 4
    for (int kq = 0; kq < 16; kq++) {
        float s0 = 0.0f, s1 = 0.0f, s2 = 0.0f, s3 = 0.0f;
#pragma unroll
        for (int b = 0; b < 16; b++)
            if (b < A) {
                float4 w = __ldg(reinterpret_cast<const float4*>(W0 + b * 64 + kq * 4));
                s0 += a[b] * w.x; s1 += a[b] * w.y; s2 += a[b] * w.z; s3 += a[b] * w.w;
            }
        h[kq * 4 + 0] = siluN(s0 * inv) * 0.125f;
        h[kq * 4 + 1] = siluN(s1 * inv) * 0.125f;
        h[kq * 4 + 2] = siluN(s2 * inv) * 0.125f;
        h[kq * 4 + 3] = siluN(s3 * inv) * 0.125f;
    }
    float* nr = g_node + n * NF;
#pragma unroll
    for (int wq = 0; wq < 4; wq++) {
        float s0 = 0.0f, s1 = 0.0f, s2 = 0.0f, s3 = 0.0f;
#pragma unroll 8
        for (int k = 0; k < 64; k++) {
            float4 w = __ldg(reinterpret_cast<const float4*>(W1 + k * 16 + wq * 4));
            float hk = h[k];
            s0 += hk * w.x; s1 += hk * w.y; s2 += hk * w.z; s3 += hk * w.w;
        }
        nr[wq * 4 + 0] = s0; nr[wq * 4 + 1] = s1;
        nr[wq * 4 + 2] = s2; nr[wq * 4 + 3] = s3;
    }
#pragma unroll
    for (int t = 0; t < 24; t++) nr[16 + t] = 0.0f;
    float* mr = g_msgs + n * NF;
#pragma unroll
    for (int t = 0; t < NF; t++) mr[t] = 0.0f;
}

// ---------------------------------------------------------------------------
// node update (float4 weight loads); re-zeroes msg row after consuming
// ---------------------------------------------------------------------------
__global__ void __launch_bounds__(64) k_update(
    int N, const float* __restrict__ imp, float degf,
    const float* __restrict__ W0, const float* __restrict__ W1, float gmul) {
    int n = blockIdx.x * blockDim.x + threadIdx.x;
    if (n >= N) return;
    float scale = imp[0] * rsqrtf(degf);
    float* nr = g_node + n * NF;
    float* mr = g_msgs + n * NF;
    float a[32];
#pragma unroll
    for (int t = 0; t < 16; t++) a[t] = mr[t] * scale;
#pragma unroll
    for (int t = 0; t < 16; t++) a[16 + t] = nr[t];
    float ge[24];
#pragma unroll
    for (int t = 0; t < 24; t++) ge[t] = (mr[16 + t] * scale + nr[16 + t]) * gmul;
#pragma unroll
    for (int t = 0; t < NF; t++) mr[t] = 0.0f;
    float h[64];
#pragma unroll 2
    for (int kq = 0; kq < 16; kq++) {
        float s0 = 0.0f, s1 = 0.0f, s2 = 0.0f, s3 = 0.0f;
#pragma unroll
        for (int b = 0; b < 32; b++) {
            float4 w = __ldg(reinterpret_cast<const float4*>(W0 + b * 64 + kq * 4));
            float ab = a[b];
            s0 += ab * w.x; s1 += ab * w.y; s2 += ab * w.z; s3 += ab * w.w;
        }
        h[kq * 4 + 0] = siluN(s0 * INV32) * 0.125f;
        h[kq * 4 + 1] = siluN(s1 * INV32) * 0.125f;
        h[kq * 4 + 2] = siluN(s2 * INV32) * 0.125f;
        h[kq * 4 + 3] = siluN(s3 * INV32) * 0.125f;
    }
    float sc[16];
#pragma unroll
    for (int wq = 0; wq < 4; wq++) {
        float s0 = 0.0f, s1 = 0.0f, s2 = 0.0f, s3 = 0.0f;
#pragma unroll 8
        for (int k = 0; k < 64; k++) {
            float4 w = __ldg(reinterpret_cast<const float4*>(W1 + k * 16 + wq * 4));
            float hk = h[k];
            s0 += hk * w.x; s1 += hk * w.y; s2 += hk * w.z; s3 += hk * w.w;
        }
        sc[wq * 4 + 0] = s0; sc[wq * 4 + 1] = s1;
        sc[wq * 4 + 2] = s2; sc[wq * 4 + 3] = s3;
    }
#pragma unroll
    for (int w = 0; w < 16; w++) nr[w] = sc[w];
#pragma unroll
    for (int t = 0; t < 24; t++) nr[16 + t] = ge[t];
}

// ---------------------------------------------------------------------------
__device__ __forceinline__ void demb_compute(float d, float* a) {
    float tt = d * 4.2f;
#pragma unroll
    for (int i = 0; i < 20; i++) {
        float diff = tt - (float)(i + 1);
        float p = diff + 1.0f, q = 1.0f - diff;
        float s1 = (p > 0.0f) ? __expf(-1.0f / p) : 0.0f;
        float s2 = (q > 0.0f) ? __expf(-1.0f / q) : 0.0f;
        a[i] = DEMBC * s1 * s2;
    }
}

// ---------------------------------------------------------------------------
// Shared edge-kernel body: smem-staged weights. Used by k_msg and k_lig.
// shS layout (floats, total SHS_F = 9216 = 36 KB):
//   scalar phase: slab rounds (8 u-cols) use [0, 8192); slices use [0, 8192)
//   vector phase: slab (C 4096 + D 2048) at [0, 6144); slices [6144, 9216)
// ---------------------------------------------------------------------------
struct EdgeCtx {
    const float* shN;   // node feats [40][EPB]
    const float* shR;   // unit vec [3][EPB]
    float* shS;
    int lane, warp, tid;
};

// fold one scalar round (8 u's of A or B) from the staged slab; p-scheme:
// p = cf * h[j] multiplies weights directly into osA/osB (no wa/wb temps).
// slab float4 layout: idx = (k*8 + uu)*4 + tq  (k = warp*KC + j)
__device__ __forceinline__ void fold_scalar_round8(
    const EdgeCtx& c, const float* ha, const float* hb,
    int u0, int isB, float* osA, float* osB)
{
    int lane = c.lane;
#pragma unroll 1
    for (int uu = 0; uu < 8; uu++) {
        int u = u0 + uu;
        float cfa, cfb;
        if (!isB) {
            cfa = C24 * c.shN[u * EPB + lane];
            cfb = C24 * c.shN[u * EPB + lane + 32];
        } else {
            cfa = C24 * (c.shN[(16 + u * 3) * EPB + lane] * c.shR[lane] +
                         c.shN[(17 + u * 3) * EPB + lane] * c.shR[EPB + lane] +
                         c.shN[(18 + u * 3) * EPB + lane] * c.shR[2 * EPB + lane]);
            cfb = C24 * (c.shN[(16 + u * 3) * EPB + lane + 32] * c.shR[lane + 32] +
                         c.shN[(17 + u * 3) * EPB + lane + 32] * c.shR[EPB + lane + 32] +
                         c.shN[(18 + u * 3) * EPB + lane + 32] * c.shR[2 * EPB + lane + 32]);
        }
#pragma unroll
        for (int j = 0; j < KC; j++) {
            float pa = cfa * ha[j];
            float pb = cfb * hb[j];
            const float4* p = reinterpret_cast<const float4*>(
                c.shS + ((c.warp * KC + j) * 8 + uu) * 16);
            float4 q0 = p[0], q1 = p[1], q2 = p[2], q3 = p[3];
            osA[0]+=pa*q0.x; osA[1]+=pa*q0.y; osA[2]+=pa*q0.z; osA[3]+=pa*q0.w;
            osA[4]+=pa*q1.x; osA[5]+=pa*q1.y; osA[6]+=pa*q1.z; osA[7]+=pa*q1.w;
            osA[8]+=pa*q2.x; osA[9]+=pa*q2.y; osA[10]+=pa*q2.z; osA[11]+=pa*q2.w;
            osA[12]+=pa*q3.x; osA[13]+=pa*q3.y; osA[14]+=pa*q3.z; osA[15]+=pa*q3.w;
            osB[0]+=pb*q0.x; osB[1]+=pb*q0.y; osB[2]+=pb*q0.z; osB[3]+=pb*q0.w;
            osB[4]+=pb*q1.x; osB[5]+=pb*q1.y; osB[6]+=pb*q1.z; osB[7]+=pb*q1.w;
            osB[8]+=pb*q2.x; osB[9]+=pb*q2.y; osB[10]+=pb*q2.z; osB[11]+=pb*q2.w;
            osB[12]+=pb*q3.x; osB[13]+=pb*q3.y; osB[14]+=pb*q3.z; osB[15]+=pb*q3.w;
        }
    }
}

// vector fold for one half from staged slab (C at [0,4096), D at [4096,6144))
__device__ __forceinline__ void fold_vector_staged(
    const EdgeCtx& c, const float* ha, const float* hb,
    float* ovA, float* ovB)
{
    int lane = c.lane;
    float ra0 = c.shR[lane],      ra1 = c.shR[EPB + lane],      ra2 = c.shR[2 * EPB + lane];
    float rb0 = c.shR[lane + 32], rb1 = c.shR[EPB + lane + 32], rb2 = c.shR[2 * EPB + lane + 32];

#pragma unroll
    for (int t = 0; t < 12; t++) { ovA[t] = 0.0f; ovB[t] = 0.0f; }

    // Block C: slab float4 idx = k*16 + u
#pragma unroll 1
    for (int u = 0; u < 16; u++) {
        float wa[4], wb[4];
#pragma unroll
        for (int t = 0; t < 4; t++) { wa[t] = 0.0f; wb[t] = 0.0f; }
#pragma unroll
        for (int j = 0; j < KC; j++) {
            float4 q = reinterpret_cast<const float4*>(c.shS)[(c.warp * KC + j) * 16 + u];
            float A = ha[j], Bv = hb[j];
            wa[0]+=A*q.x; wa[1]+=A*q.y; wa[2]+=A*q.z; wa[3]+=A*q.w;
            wb[0]+=Bv*q.x; wb[1]+=Bv*q.y; wb[2]+=Bv*q.z; wb[3]+=Bv*q.w;
        }
        float cfa = C24S3 * c.shN[u * EPB + lane];
        float cfb = C24S3 * c.shN[u * EPB + lane + 32];
#pragma unroll
        for (int t = 0; t < 4; t++) {
            float sa = cfa * wa[t], sb = cfb * wb[t];
            ovA[t*3+0] += sa * ra0; ovA[t*3+1] += sa * ra1; ovA[t*3+2] += sa * ra2;
            ovB[t*3+0] += sb * rb0; ovB[t*3+1] += sb * rb1; ovB[t*3+2] += sb * rb2;
        }
    }

    // Block D: slab float4 idx = 1024 + k*8 + u
#pragma unroll 1
    for (int u = 0; u < 8; u++) {
        float wa[4], wb[4];
#pragma unroll
        for (int t = 0; t < 4; t++) { wa[t] = 0.0f; wb[t] = 0.0f; }
#pragma unroll
        for (int j = 0; j < KC; j++) {
            float4 q = reinterpret_cast<const float4*>(c.shS)[1024 + (c.warp * KC + j) * 8 + u];
            float A = ha[j], Bv = hb[j];
            wa[0]+=A*q.x; wa[1]+=A*q.y; wa[2]+=A*q.z; wa[3]+=A*q.w;
            wb[0]+=Bv*q.x; wb[1]+=Bv*q.y; wb[2]+=Bv*q.z; wb[3]+=Bv*q.w;
        }
        float ca0 = C24 * c.shN[(16 + u * 3) * EPB + lane];
        float ca1 = C24 * c.shN[(17 + u * 3) * EPB + lane];
        float ca2 = C24 * c.shN[(18 + u * 3) * EPB + lane];
        float cb0 = C24 * c.shN[(16 + u * 3) * EPB + lane + 32];
        float cb1 = C24 * c.shN[(17 + u * 3) * EPB + lane + 32];
        float cb2 = C24 * c.shN[(18 + u * 3) * EPB + lane + 32];
#pragma unroll
        for (int t = 0; t < 4; t++) {
            ovA[t*3+0] += ca0 * wa[t]; ovA[t*3+1] += ca1 * wa[t]; ovA[t*3+2] += ca2 * wa[t];
            ovB[t*3+0] += cb0 * wb[t]; ovB[t*3+1] += cb1 * wb[t]; ovB[t*3+2] += cb2 * wb[t];
        }
    }
}

// stage one scalar slab round (8 u-columns, all 64 k) coalesced
__device__ __forceinline__ void stage_scalar8(
    float* shS, const float* __restrict__ W1, int colbase, int tid)
{
    for (int i4 = tid; i4 < 2048; i4 += TBE) {
        int tq = (i4 & 3) * 4, uu = (i4 >> 2) & 7, k = i4 >> 5;
        float4 v = __ldg(reinterpret_cast<const float4*>(W1 + k * 576 + colbase + uu * 16 + tq));
        reinterpret_cast<float4*>(shS)[i4] = v;
    }
}

// stage vector slab for one half (C: 16 u, D: 8 u)
__device__ __forceinline__ void stage_vector(
    float* shS, const float* __restrict__ W1, int half, int tid)
{
    for (int i4 = tid; i4 < 1024; i4 += TBE) {           // C
        int k = i4 >> 4, u = i4 & 15;
        float4 v = __ldg(reinterpret_cast<const float4*>(W1 + k * 576 + 384 + u * 8 + half * 4));
        reinterpret_cast<float4*>(shS)[i4] = v;
    }
    for (int i4 = tid; i4 < 512; i4 += TBE) {            // D
        int k = i4 >> 3, u = i4 & 7;
        float4 v = __ldg(reinterpret_cast<const float4*>(W1 + k * 576 + 512 + u * 8 + half * 4));
        reinterpret_cast<float4*>(shS)[1024 + i4] = v;
    }
}

// ---------------------------------------------------------------------------
// message kernel: 64 edges / 256 threads, smem-staged weights, 3 blocks/SM
// ---------------------------------------------------------------------------
__global__ void __launch_bounds__(TBE, 3) k_msg(
    const float* __restrict__ pos,
    const int* __restrict__ srcI, const int* __restrict__ dstI,
    const float* __restrict__ eattr, int E, int B,
    const float* __restrict__ W0, const float* __restrict__ W1)
{
    __shared__ float shN[NF * EPB];          // 10 KB
    __shared__ float shS[SHS_F];             // 36 KB union slab/slice
    __shared__ float shR[3 * EPB];
    __shared__ int   shSi[EPB];
    __shared__ int   shDi[EPB];

    int tid  = threadIdx.x;
    int lane = tid & 31;
    int warp = tid >> 5;
    int e0 = blockIdx.x * EPB;

    if (tid < EPB) {
        int e = min(e0 + tid, E - 1);
        int si = srcI[e], di = dstI[e];
        shSi[tid] = si; shDi[tid] = di;
        float vx = pos[di * 3 + 0] - pos[si * 3 + 0];
        float vy = pos[di * 3 + 1] - pos[si * 3 + 1];
        float vz = pos[di * 3 + 2] - pos[si * 3 + 2];
        float rn = rsqrtf(vx * vx + vy * vy + vz * vz);
        shR[tid]           = vx * rn;
        shR[EPB + tid]     = vy * rn;
        shR[2 * EPB + tid] = vz * rn;
    }
    __syncthreads();

    for (int i = tid; i < NF * EPB; i += TBE) {
        int e = i & (EPB - 1), f = i >> 6;
        shN[f * EPB + e] = g_node[shSi[e] * NF + f];
    }

    float ha[KC], hb[KC];
    {
        float inv = rsqrtf((float)B);
        int kb = warp * KC;
        int ea = min(e0 + lane, E - 1);
        int eb = min(e0 + lane + 32, E - 1);
        float aa[8], ab[8];
#pragma unroll
        for (int b = 0; b < 8; b++) {
            aa[b] = (b < B) ? eattr[ea * B + b] : 0.0f;
            ab[b] = (b < B) ? eattr[eb * B + b] : 0.0f;
        }
#pragma unroll
        for (int j = 0; j < KC; j++) {
            float sa = 0.0f, sb = 0.0f;
#pragma unroll
            for (int b = 0; b < 8; b++)
                if (b < B) {
                    float w = W0[b * 64 + kb + j];
                    sa += aa[b] * w; sb += ab[b] * w;
                }
            ha[j] = siluN(sa * inv) * 0.125f;
            hb[j] = siluN(sb * inv) * 0.125f;
        }
    }

    EdgeCtx ctx{shN, shR, shS, lane, warp, tid};

    // ---- scalar phase: 3 slab rounds (A u0=0; A u0=8; B u0=0) ----
    float osA[16], osB[16];
#pragma unroll
    for (int t = 0; t < 16; t++) { osA[t] = 0.0f; osB[t] = 0.0f; }
#pragma unroll 1
    for (int round = 0; round < 3; round++) {
        int isB = (round == 2);
        int u0 = (round == 1) ? 8 : 0;
        int colbase = isB ? 256 : u0 * 16;
        __syncthreads();
        stage_scalar8(shS, W1, colbase, tid);
        __syncthreads();
        fold_scalar_round8(ctx, ha, hb, u0, isB, osA, osB);
    }
    __syncthreads();
#pragma unroll
    for (int t = 0; t < 16; t++) {
        shS[warp * 16 * EPB + t * EPB + lane]      = osA[t];
        shS[warp * 16 * EPB + t * EPB + lane + 32] = osB[t];
    }
    __syncthreads();
    for (int i = tid; i < 16 * EPB; i += TBE) {
        float s = 0.0f;
#pragma unroll
        for (int w = 0; w < NW; w++) s += shS[w * 16 * EPB + i];
        int e = i & (EPB - 1), f = i >> 6;
        if (e0 + e < E) atomicAdd(&g_msgs[shDi[e] * NF + f], s);
    }

    // ---- vector phases (2 halves; slab [0,6144), slices [6144,9216)) ----
#pragma unroll 1
    for (int half = 0; half < 2; half++) {
        __syncthreads();
        stage_vector(shS, W1, half, tid);
        __syncthreads();
        float ovA[12], ovB[12];
        fold_vector_staged(ctx, ha, hb, ovA, ovB);
#pragma unroll 1
        for (int cch = 0; cch < 2; cch++) {
            __syncthreads();
#pragma unroll
            for (int t = 0; t < 6; t++) {
                shS[6144 + warp * 6 * EPB + t * EPB + lane]      = ovA[cch * 6 + t];
                shS[6144 + warp * 6 * EPB + t * EPB + lane + 32] = ovB[cch * 6 + t];
            }
            __syncthreads();
            for (int i = tid; i < 6 * EPB; i += TBE) {
                float s = 0.0f;
#pragma unroll
                for (int w = 0; w < NW; w++) s += shS[6144 + w * 6 * EPB + i];
                int e = i & (EPB - 1), f = i >> 6;
                if (e0 + e < E)
                    atomicAdd(&g_msgs[shDi[e] * NF + 16 + half * 12 + cch * 6 + f], s);
            }
        }
    }
}

// ---------------------------------------------------------------------------
// ligand embedding (same staging); also zeroes d_out rows for k_rec
// ---------------------------------------------------------------------------
__global__ void __launch_bounds__(TBE, 3) k_lig(
    const float* __restrict__ pos,
    const int* __restrict__ recI, const int* __restrict__ ligI, int EI,
    const float* __restrict__ W0, const float* __restrict__ W1,
    float* __restrict__ out)
{
    __shared__ float shN[NF * EPB];
    __shared__ float shS[SHS_F];
    __shared__ float shR[3 * EPB];
    __shared__ float shD[EPB];
    __shared__ int   shLi[EPB];

    int tid  = threadIdx.x;
    int lane = tid & 31;
    int warp = tid >> 5;
    int e0 = blockIdx.x * EPB;

    for (int i = tid; i < 8 * EPB; i += TBE) {
        int e = i >> 3;
        if (e0 + e < EI) out[(e0 + e) * 8 + (i & 7)] = 0.0f;
    }

    if (tid < EPB) {
        int e = min(e0 + tid, EI - 1);
        int ri = recI[e], li = ligI[e];
        shLi[tid] = li;
        float vx = pos[li * 3 + 0] - pos[ri * 3 + 0];
        float vy = pos[li * 3 + 1] - pos[ri * 3 + 1];
        float vz = pos[li * 3 + 2] - pos[ri * 3 + 2];
        float d2 = vx * vx + vy * vy + vz * vz;
        float invd = rsqrtf(d2);
        shR[tid]           = vx * invd;
        shR[EPB + tid]     = vy * invd;
        shR[2 * EPB + tid] = vz * invd;
        shD[tid]           = d2 * invd;
    }
    __syncthreads();

    for (int i = tid; i < NF * EPB; i += TBE) {
        int e = i & (EPB - 1), f = i >> 6;
        shN[f * EPB + e] = g_node[shLi[e] * NF + f];
    }

    float ha[KC], hb[KC];
    {
        int kb = warp * KC;
        float aa[20], ab[20];
        demb_compute(shD[lane],      aa);
        demb_compute(shD[lane + 32], ab);
#pragma unroll
        for (int j = 0; j < KC; j++) {
            float sa = 0.0f, sb = 0.0f;
#pragma unroll
            for (int i = 0; i < 20; i++) {
                float w = W0[i * 64 + kb + j];
                sa += aa[i] * w; sb += ab[i] * w;
            }
            ha[j] = siluN(sa) * 0.125f;
            hb[j] = siluN(sb) * 0.125f;
        }
    }

    EdgeCtx ctx{shN, shR, shS, lane, warp, tid};

    float osA[16], osB[16];
#pragma unroll
    for (int t = 0; t < 16; t++) { osA[t] = 0.0f; osB[t] = 0.0f; }
#pragma unroll 1
    for (int round = 0; round < 3; round++) {
        int isB = (round == 2);
        int u0 = (round == 1) ? 8 : 0;
        int colbase = isB ? 256 : u0 * 16;
        __syncthreads();
        stage_scalar8(shS, W1, colbase, tid);
        __syncthreads();
        fold_scalar_round8(ctx, ha, hb, u0, isB, osA, osB);
    }
    __syncthreads();
#pragma unroll
    for (int t = 0; t < 16; t++) {
        shS[warp * 16 * EPB + t * EPB + lane]      = osA[t];
        shS[warp * 16 * EPB + t * EPB + lane + 32] = osB[t];
    }
    __syncthreads();
    for (int i = tid; i < 16 * EPB; i += TBE) {
        float s = 0.0f;
#pragma unroll
        for (int w = 0; w < NW; w++) s += shS[w * 16 * EPB + i];
        int e = i & (EPB - 1), f = i >> 6;
        if (e0 + e < EI) g_lig[(e0 + e) * NF + f] = s;
    }

#pragma unroll 1
    for (int half = 0; half < 2; half++) {
        __syncthreads();
        stage_vector(shS, W1, half, tid);
        __syncthreads();
        float ovA[12], ovB[12];
        fold_vector_staged(ctx, ha, hb, ovA, ovB);
#pragma unroll 1
        for (int cch = 0; cch < 2; cch++) {
            __syncthreads();
#pragma unroll
            for (int t = 0; t < 6; t++) {
                shS[6144 + warp * 6 * EPB + t * EPB + lane]      = ovA[cch * 6 + t];
                shS[6144 + warp * 6 * EPB + t * EPB + lane + 32] = ovB[cch * 6 + t];
            }
            __syncthreads();
            for (int i = tid; i < 6 * EPB; i += TBE) {
                float s = 0.0f;
#pragma unroll
                for (int w = 0; w < NW; w++) s += shS[6144 + w * 6 * EPB + i];
                int e = i & (EPB - 1), f = i >> 6;
                if (e0 + e < EI)
                    g_lig[(e0 + e) * NF + 16 + half * 12 + cch * 6 + f] = s;
            }
        }
    }
}

// ---------------------------------------------------------------------------
// receptor TP readout (R13): 128 edges/block, 4 slots/lane, gridDim.y=2
// ---------------------------------------------------------------------------
__global__ void __launch_bounds__(TBE, 2) k_rec(
    const float* __restrict__ pos,
    const int* __restrict__ recI, const int* __restrict__ ligI, int EI,
    const float* __restrict__ W0, const float* __restrict__ W1,
    float* __restrict__ out)
{
    __shared__ float shL [NF * EPR];
    __shared__ float shRn[NF * EPR];
    __shared__ float shD [EPR];
    __shared__ int   shRi[EPR];

    int tid  = threadIdx.x;
    int lane = tid & 31;
    int warp = tid >> 5;
    int e0 = blockIdx.x * EPR;
    int kb = warp * KCR + blockIdx.y * 32;

    if (tid < EPR) {
        int e = min(e0 + tid, EI - 1);
        int ri = recI[e], li = ligI[e];
        shRi[tid] = ri;
        float vx = pos[li * 3 + 0] - pos[ri * 3 + 0];
        float vy = pos[li * 3 + 1] - pos[ri * 3 + 1];
        float vz = pos[li * 3 + 2] - pos[ri * 3 + 2];
        float d2 = vx * vx + vy * vy + vz * vz;
        shD[tid] = d2 * rsqrtf(d2);
    }
    __syncthreads();

    for (int i = tid; i < NF * EPR; i += TBE) {
        int e = i & (EPR - 1), f = i >> 7;
        int ec = min(e0 + e, EI - 1);
        shL [f * EPR + e] = g_lig[ec * NF + f];
        shRn[f * EPR + e] = g_node[shRi[e] * NF + f];
    }

    float h[4][KCR];
    {
#pragma unroll 1
        for (int s = 0; s < 4; s++) {
            float aa[20];
            demb_compute(shD[lane + s * 32], aa);
#pragma unroll
            for (int j = 0; j < KCR; j++) {
                float sm = 0.0f;
#pragma unroll
                for (int i = 0; i < 20; i++) sm += aa[i] * W0[i * 64 + kb + j];
                h[s][j] = siluN(sm) * 0.125f;
            }
        }
    }
    __syncthreads();

    float acc[4][8];
#pragma unroll
    for (int s = 0; s < 4; s++)
#pragma unroll
        for (int t = 0; t < 8; t++) acc[s][t] = 0.0f;
    const float* Wk = W1 + kb * 2560;

#pragma unroll 1
    for (int u = 0; u < 16; u++) {
        float lu[4];
#pragma unroll
        for (int s = 0; s < 4; s++) lu[s] = shL[u * EPR + lane + s * 32];
#pragma unroll 1
        for (int v = 0; v < 16; v++) {
            float cf[4];
#pragma unroll
            for (int s = 0; s < 4; s++) cf[s] = lu[s] * shRn[v * EPR + lane + s * 32];
            const float* base = Wk + (u * 16 + v) * 8;
#pragma unroll
            for (int j = 0; j < KCR; j++) {
                float p[4];
#pragma unroll
                for (int s = 0; s < 4; s++) p[s] = cf[s] * h[s][j];
                const float4* bp = reinterpret_cast<const float4*>(base + j * 2560);
                float4 q0 = __ldg(bp), q1 = __ldg(bp + 1);
#pragma unroll
                for (int s = 0; s < 4; s++) {
                    acc[s][0] += p[s] * q0.x; acc[s][1] += p[s] * q0.y;
                    acc[s][2] += p[s] * q0.z; acc[s][3] += p[s] * q0.w;
                    acc[s][4] += p[s] * q1.x; acc[s][5] += p[s] * q1.y;
                    acc[s][6] += p[s] * q1.z; acc[s][7] += p[s] * q1.w;
                }
            }
        }
    }

#pragma unroll 1
    for (int u = 0; u < 8; u++) {
        float la0[4], la1[4], la2[4];
#pragma unroll
        for (int s = 0; s < 4; s++) {
            int idx = lane + s * 32;
            la0[s] = shL[(16 + u * 3) * EPR + idx];
            la1[s] = shL[(17 + u * 3) * EPR + idx];
            la2[s] = shL[(18 + u * 3) * EPR + idx];
        }
#pragma unroll 1
        for (int v = 0; v < 8; v++) {
            float cf[4];
#pragma unroll
            for (int s = 0; s < 4; s++) {
                int idx = lane + s * 32;
                cf[s] = (la0[s] * shRn[(16 + v * 3) * EPR + idx] +
                         la1[s] * shRn[(17 + v * 3) * EPR + idx] +
                         la2[s] * shRn[(18 + v * 3) * EPR + idx]) * INVS3;
            }
            const float* base = Wk + 2048 + (u * 8 + v) * 8;
#pragma unroll
            for (int j = 0; j < KCR; j++) {
                float p[4];
#pragma unroll
                for (int s = 0; s < 4; s++) p[s] = cf[s] * h[s][j];
                const float4* bp = reinterpret_cast<const float4*>(base + j * 2560);
                float4 q0 = __ldg(bp), q1 = __ldg(bp + 1);
#pragma unroll
                for (int s = 0; s < 4; s++) {
                    acc[s][0] += p[s] * q0.x; acc[s][1] += p[s] * q0.y;
                    acc[s][2] += p[s] * q0.z; acc[s][3] += p[s] * q0.w;
                    acc[s][4] += p[s] * q1.x; acc[s][5] += p[s] * q1.y;
                    acc[s][6] += p[s] * q1.z; acc[s][7] += p[s] * q1.w;
                }
            }
        }
    }

#pragma unroll
    for (int s = 0; s < 4; s++) {
        int e = e0 + lane + s * 32;
        if (e < EI) {
#pragma unroll
            for (int t = 0; t < 8; t++)
                atomicAdd(&out[e * 8 + t], PWREC * acc[s][t]);
        }
    }
}

// ---------------------------------------------------------------------------
// host launcher (graph-capturable: kernel launches only)
// ---------------------------------------------------------------------------
extern "C" void kernel_launch(void* const* d_in, const int* in_sizes, int n_in,
                              void* d_out, int out_size) {
    (void)n_in; (void)out_size;
    const float* x       = (const float*)d_in[0];
    const float* pos     = (const float*)d_in[1];
    const int*   eidx    = (const int*)  d_in[2];
    const float* eattr   = (const float*)d_in[3];
    const int*   iidx    = (const int*)  d_in[4];
    const float* emb_w0  = (const float*)d_in[5];
    const float* emb_w1  = (const float*)d_in[6];
    const float* imp0    = (const float*)d_in[7];
    const float* msg0_w0 = (const float*)d_in[8];
    const float* msg0_w1 = (const float*)d_in[9];
    const float* upd0_w0 = (const float*)d_in[10];
    const float* upd0_w1 = (const float*)d_in[11];
    const float* imp1    = (const float*)d_in[12];
    const float* msg1_w0 = (const float*)d_in[13];
    const float* msg1_w1 = (const float*)d_in[14];
    const float* upd1_w0 = (const float*)d_in[15];
    const float* upd1_w1 = (const float*)d_in[16];
    const float* lig_w0  = (const float*)d_in[17];
    const float* lig_w1  = (const float*)d_in[18];
    const float* rec_w0  = (const float*)d_in[19];
    const float* rec_w1  = (const float*)d_in[20];

    int N  = in_sizes[1] / 3;
    int A  = in_sizes[0] / N;
    int E  = in_sizes[2] / 2;
    int B  = in_sizes[3] / E;
    int EI = in_sizes[4] / 2;
    const int* src  = eidx;
    const int* dst  = eidx + E;
    const int* recI = iidx;
    const int* ligI = iidx + EI;
    float degf = (float)E / (float)N;

    int gn = (N + 63) / 64;
    int ge = (E + EPB - 1) / EPB;
    int gi = (EI + EPB - 1) / EPB;
    dim3 gr((EI + EPR - 1) / EPR, 2);

    k_embed<<<gn, 64>>>(x, N, A, emb_w0, emb_w1);       // also zeroes g_msgs

    k_msg<<<ge, TBE>>>(pos, src, dst, eattr, E, B, msg0_w0, msg0_w1);
    k_update<<<gn, 64>>>(N, imp0, degf, upd0_w0, upd0_w1, 1.0f);   // re-zeroes g_msgs

    k_msg<<<ge, TBE>>>(pos, src, dst, eattr, E, B, msg1_w0, msg1_w1);
    k_update<<<gn, 64>>>(N, imp1, degf, upd1_w0, upd1_w1, 0.5f);

    k_lig<<<gi, TBE>>>(pos, recI, ligI, EI, lig_w0, lig_w1, (float*)d_out);  // zeroes d_out
    k_rec<<<gr, TBE>>>(pos, recI, ligI, EI, rec_w0, rec_w1, (float*)d_out);
}